// round 1
// baseline (speedup 1.0000x reference)
#include <cuda_runtime.h>

// Problem constants
#define BLN 8192       // B*L = 8*1024
#define DIM 1024       // D
#define QKSCALE 0.03125f  // 1/sqrt(1024)

// Scratch (device globals: allocation-free per harness rules). 4 x 32MB.
__device__ float g_Q[BLN * DIM];
__device__ float g_K[BLN * DIM];
__device__ float g_V[BLN * DIM];
__device__ float g_A[BLN * DIM];

// ---------------------------------------------------------------------------
// Generic GEMM: C[M=8192,1024] = (A[8192,1024] @ W[1024,1024] + bias) * scale
// 128x128 tile, BK=16, 256 threads, 8x8 per-thread microtile.
// ---------------------------------------------------------------------------
__global__ __launch_bounds__(256, 2)
void gemm_bias_kernel(const float* __restrict__ A, const float* __restrict__ W,
                      const float* __restrict__ bias, float* __restrict__ C,
                      float scale) {
    __shared__ float As[16][128];   // transposed A tile: As[k][m]
    __shared__ float Bs[16][128];   // Bs[k][n]

    const int tid = threadIdx.x;
    const int m0 = blockIdx.y << 7;
    const int n0 = blockIdx.x << 7;
    const int ty = tid >> 4;        // 0..15  -> rows ty*8..+7
    const int tx = tid & 15;        // 0..15  -> cols tx*8..+7

    float acc[8][8];
#pragma unroll
    for (int i = 0; i < 8; i++)
#pragma unroll
        for (int j = 0; j < 8; j++) acc[i][j] = 0.f;

    for (int k0 = 0; k0 < 1024; k0 += 16) {
        // Load A tile (128 rows x 16 cols), store transposed
#pragma unroll
        for (int i = 0; i < 2; i++) {
            int q = tid + (i << 8);          // 0..511 float4 slots
            int row = q >> 2, c4 = q & 3;
            float4 v = *(const float4*)(A + (m0 + row) * 1024 + k0 + (c4 << 2));
            As[(c4 << 2) + 0][row] = v.x;
            As[(c4 << 2) + 1][row] = v.y;
            As[(c4 << 2) + 2][row] = v.z;
            As[(c4 << 2) + 3][row] = v.w;
        }
        // Load B tile (16 rows x 128 cols)
#pragma unroll
        for (int i = 0; i < 2; i++) {
            int q = tid + (i << 8);
            int row = q >> 5, c4 = q & 31;
            *(float4*)(&Bs[row][c4 << 2]) =
                *(const float4*)(W + (k0 + row) * 1024 + n0 + (c4 << 2));
        }
        __syncthreads();

#pragma unroll
        for (int k = 0; k < 16; k++) {
            float4 a0 = *(const float4*)(&As[k][ty << 3]);
            float4 a1 = *(const float4*)(&As[k][(ty << 3) + 4]);
            float4 b0 = *(const float4*)(&Bs[k][tx << 3]);
            float4 b1 = *(const float4*)(&Bs[k][(tx << 3) + 4]);
            float av[8] = {a0.x, a0.y, a0.z, a0.w, a1.x, a1.y, a1.z, a1.w};
            float bv[8] = {b0.x, b0.y, b0.z, b0.w, b1.x, b1.y, b1.z, b1.w};
#pragma unroll
            for (int i = 0; i < 8; i++)
#pragma unroll
                for (int j = 0; j < 8; j++) acc[i][j] += av[i] * bv[j];
        }
        __syncthreads();
    }

#pragma unroll
    for (int i = 0; i < 8; i++) {
        int m = m0 + (ty << 3) + i;
#pragma unroll
        for (int j = 0; j < 8; j += 4) {
            int n = n0 + (tx << 3) + j;
            float4 o;
            o.x = (acc[i][j + 0] + bias[n + 0]) * scale;
            o.y = (acc[i][j + 1] + bias[n + 1]) * scale;
            o.z = (acc[i][j + 2] + bias[n + 2]) * scale;
            o.w = (acc[i][j + 3] + bias[n + 3]) * scale;
            *(float4*)(C + m * 1024 + n) = o;
        }
    }
}

// ---------------------------------------------------------------------------
// Fused attention per group g=(b,h):
//   S[t1,t2] = sum_d Q[b,h*64+d,t1] * K[b,h*64+d,t2]     (t1 tile of 32, t2 full 1024)
//   P = softmax_rows(S)
//   O[t1,d]  = sum_t2 P[t1,t2] * V[b,h*64+d,t2]
// One CTA = (group, 32-row q tile). S kept fully in smem -> exact softmax.
// ---------------------------------------------------------------------------
#define ATT_S_FLOATS   (32 * 1024)
#define ATT_Q_FLOATS   (64 * 32)
#define ATT_KV_FLOATS  (128 * 68)
#define ATT_SMEM_BYTES ((ATT_S_FLOATS + ATT_Q_FLOATS + ATT_KV_FLOATS) * 4)

__global__ __launch_bounds__(256, 1)
void attn_kernel() {
    extern __shared__ float sm[];
    float* S  = sm;                          // [32][1024]
    float* Qt = sm + ATT_S_FLOATS;           // [64][32]   Qt[d][i]
    float* KV = Qt + ATT_Q_FLOATS;           // K: [64][128]  /  V^T: [128][68]

    const int g  = blockIdx.y;               // 0..127
    const int qt = blockIdx.x;               // 0..31
    const int b  = g >> 4;
    const int h  = g & 15;
    const int base = (b << 20) + ((h << 6) << 10);   // b*1048576 + h*64*1024
    const float* Qb = g_Q + base;
    const float* Kb = g_K + base;
    const float* Vb = g_V + base;
    const int tid = threadIdx.x;

    // ---- Load Q tile: Qt[d][i] = Q[b, h*64+d, qt*32+i], 64x32 floats ----
#pragma unroll
    for (int i = 0; i < 2; i++) {
        int q = tid + (i << 8);              // 0..511 float4 slots
        int d = q >> 3, c4 = q & 7;
        float4 v = *(const float4*)(Qb + d * 1024 + (qt << 5) + (c4 << 2));
        *(float4*)(&Qt[d * 32 + (c4 << 2)]) = v;
    }

    // ---- S = Qt^T @ K, k-tiles of 128 columns ----
    {
        const int ty = tid >> 5;             // 0..7   rows ty*4..+3
        const int tx = tid & 31;             // 0..31  cols tx*4..+3
        for (int kc = 0; kc < 8; kc++) {
            // K tile [64][128]
#pragma unroll
            for (int i = 0; i < 8; i++) {
                int q = tid + (i << 8);      // 0..2047 float4 slots
                int d = q >> 5, c4 = q & 31;
                *(float4*)(&KV[d * 128 + (c4 << 2)]) =
                    *(const float4*)(Kb + d * 1024 + (kc << 7) + (c4 << 2));
            }
            __syncthreads();                 // also covers Qt on first iter

            float acc[4][4];
#pragma unroll
            for (int i = 0; i < 4; i++)
#pragma unroll
                for (int j = 0; j < 4; j++) acc[i][j] = 0.f;

#pragma unroll 8
            for (int d = 0; d < 64; d++) {
                float4 a = *(const float4*)(&Qt[d * 32 + (ty << 2)]);
                float4 k4 = *(const float4*)(&KV[d * 128 + (tx << 2)]);
                float av[4] = {a.x, a.y, a.z, a.w};
                float kv[4] = {k4.x, k4.y, k4.z, k4.w};
#pragma unroll
                for (int i = 0; i < 4; i++)
#pragma unroll
                    for (int j = 0; j < 4; j++) acc[i][j] += av[i] * kv[j];
            }
#pragma unroll
            for (int i = 0; i < 4; i++) {
                *(float4*)(&S[((ty << 2) + i) * 1024 + (kc << 7) + (tx << 2)]) =
                    make_float4(acc[i][0], acc[i][1], acc[i][2], acc[i][3]);
            }
            __syncthreads();
        }
    }

    // ---- softmax over each of the 32 rows (1 warp per 4 rows) ----
    {
        const int w = tid >> 5, lane = tid & 31;
#pragma unroll
        for (int rr = 0; rr < 4; rr++) {
            float* row = S + ((w << 2) + rr) * 1024;
            float m = -1e30f;
            for (int c = lane; c < 1024; c += 32) m = fmaxf(m, row[c]);
#pragma unroll
            for (int o = 16; o > 0; o >>= 1) m = fmaxf(m, __shfl_xor_sync(0xffffffffu, m, o));
            float s = 0.f;
            for (int c = lane; c < 1024; c += 32) {
                float e = __expf(row[c] - m);
                row[c] = e;
                s += e;
            }
#pragma unroll
            for (int o = 16; o > 0; o >>= 1) s += __shfl_xor_sync(0xffffffffu, s, o);
            float inv = 1.0f / s;
            for (int c = lane; c < 1024; c += 32) row[c] *= inv;
        }
    }
    __syncthreads();

    // ---- O = P @ V^T (V transposed into smem, conflict-free) ----
    {
        const int ty2 = tid >> 4;            // 0..15  rows ty2*2..+1
        const int tx2 = tid & 15;            // cols tx2*4..+3 (d)
        float acc[2][4];
#pragma unroll
        for (int i = 0; i < 2; i++)
#pragma unroll
            for (int j = 0; j < 4; j++) acc[i][j] = 0.f;

        for (int kc = 0; kc < 8; kc++) {
            // Load V^T tile: KV[t2][d] (stride 68). Each thread: 4 scalar global
            // loads (d0..d0+3 at one t2) -> one float4 smem store; consecutive
            // lanes own consecutive t2 -> coalesced loads, conflict-free stores.
#pragma unroll
            for (int i = 0; i < 8; i++) {
                int q = tid + (i << 8);      // 0..2047
                int t2 = q & 127;
                int d0 = (q >> 7) << 2;      // 0,4,...,60
                float4 v;
                v.x = Vb[(d0 + 0) * 1024 + (kc << 7) + t2];
                v.y = Vb[(d0 + 1) * 1024 + (kc << 7) + t2];
                v.z = Vb[(d0 + 2) * 1024 + (kc << 7) + t2];
                v.w = Vb[(d0 + 3) * 1024 + (kc << 7) + t2];
                *(float4*)(&KV[t2 * 68 + d0]) = v;
            }
            __syncthreads();

            const float* Srow0 = S + (ty2 << 1) * 1024 + (kc << 7);
            const float* Srow1 = Srow0 + 1024;
#pragma unroll 4
            for (int t2 = 0; t2 < 128; t2 += 4) {
                float4 s0 = *(const float4*)(Srow0 + t2);
                float4 s1 = *(const float4*)(Srow1 + t2);
                float s0a[4] = {s0.x, s0.y, s0.z, s0.w};
                float s1a[4] = {s1.x, s1.y, s1.z, s1.w};
#pragma unroll
                for (int u = 0; u < 4; u++) {
                    float4 v = *(const float4*)(&KV[(t2 + u) * 68 + (tx2 << 2)]);
                    float vv[4] = {v.x, v.y, v.z, v.w};
#pragma unroll
                    for (int j = 0; j < 4; j++) {
                        acc[0][j] += s0a[u] * vv[j];
                        acc[1][j] += s1a[u] * vv[j];
                    }
                }
            }
            __syncthreads();
        }

        // Scatter O[t1,d] -> a[b, h*64 + t1/16, (t1%16)*64 + d]
#pragma unroll
        for (int i = 0; i < 2; i++) {
            int t1 = (qt << 5) + (ty2 << 1) + i;
            int p = t1 >> 4, qq = t1 & 15;
            float* dst = g_A + (b << 20) + ((h << 6) + p) * 1024 + (qq << 6) + (tx2 << 2);
            *(float4*)dst = make_float4(acc[i][0], acc[i][1], acc[i][2], acc[i][3]);
        }
    }
}

// ---------------------------------------------------------------------------
extern "C" void kernel_launch(void* const* d_in, const int* in_sizes, int n_in,
                              void* d_out, int out_size) {
    const float* x  = (const float*)d_in[0];
    const float* Wq = (const float*)d_in[1];
    const float* bq = (const float*)d_in[2];
    const float* Wk = (const float*)d_in[3];
    const float* bk = (const float*)d_in[4];
    const float* Wv = (const float*)d_in[5];
    const float* bv = (const float*)d_in[6];
    const float* Wo = (const float*)d_in[7];
    const float* bo = (const float*)d_in[8];
    float* out = (float*)d_out;

    float *Qp, *Kp, *Vp, *Ap;
    cudaGetSymbolAddress((void**)&Qp, g_Q);
    cudaGetSymbolAddress((void**)&Kp, g_K);
    cudaGetSymbolAddress((void**)&Vp, g_V);
    cudaGetSymbolAddress((void**)&Ap, g_A);

    // Opt-in to 174KB dynamic smem for the attention kernel (idempotent).
    cudaFuncSetAttribute(attn_kernel, cudaFuncAttributeMaxDynamicSharedMemorySize,
                         ATT_SMEM_BYTES);

    dim3 gemm_grid(8, 64);   // N/128, M/128

    gemm_bias_kernel<<<gemm_grid, 256>>>(x, Wq, bq, Qp, QKSCALE);
    gemm_bias_kernel<<<gemm_grid, 256>>>(x, Wk, bk, Kp, QKSCALE);
    gemm_bias_kernel<<<gemm_grid, 256>>>(x, Wv, bv, Vp, 1.0f);

    attn_kernel<<<dim3(32, 128), 256, ATT_SMEM_BYTES>>>();

    gemm_bias_kernel<<<gemm_grid, 256>>>(Ap, Wo, bo, out, 1.0f);
}

// round 4
// speedup vs baseline: 1.3965x; 1.3965x over previous
#include <cuda_runtime.h>
#include <cuda_bf16.h>
#include <cstdint>

// ===========================================================================
// Problem constants
// ===========================================================================
#define BLN 8192          // B*L
#define DIM 1024          // D
#define QKSCALE 0.03125f  // 1/sqrt(1024)

// ===========================================================================
// Device scratch (allocation-free rule: device globals)
// ===========================================================================
__device__ float g_Q[BLN * DIM];
__device__ float g_K[BLN * DIM];
__device__ float g_V[BLN * DIM];
__device__ float g_A[BLN * DIM];
__device__ __nv_bfloat16 g_xhi[BLN * DIM];
__device__ __nv_bfloat16 g_xlo[BLN * DIM];
__device__ __nv_bfloat16 g_ahi[BLN * DIM];
__device__ __nv_bfloat16 g_alo[BLN * DIM];
__device__ __nv_bfloat16 g_wt_hi[4][DIM * DIM];   // W^T [n][k] hi
__device__ __nv_bfloat16 g_wt_lo[4][DIM * DIM];   // W^T [n][k] lo

// ===========================================================================
// PTX helpers (sm_80-era only: mma.sync / ldmatrix / cp.async — plain sm_100
// target rejects tcgen05.*)
// ===========================================================================
__device__ __forceinline__ uint32_t smem_u32(const void* p) {
    uint32_t a;
    asm("{ .reg .u64 t; cvta.to.shared.u64 t, %1; cvt.u32.u64 %0, t; }" : "=r"(a) : "l"(p));
    return a;
}
#define CP_ASYNC16(saddr, gptr) \
    asm volatile("cp.async.cg.shared.global [%0], [%1], 16;" :: "r"(saddr), "l"(gptr))
#define CP_COMMIT() asm volatile("cp.async.commit_group;" ::: "memory")
#define CP_WAIT(n)  asm volatile("cp.async.wait_group %0;" :: "n"(n) : "memory")

__device__ __forceinline__ void ldmx4(uint32_t& r0, uint32_t& r1, uint32_t& r2, uint32_t& r3,
                                      uint32_t addr) {
    asm volatile("ldmatrix.sync.aligned.m8n8.x4.shared.b16 {%0,%1,%2,%3}, [%4];"
                 : "=r"(r0), "=r"(r1), "=r"(r2), "=r"(r3) : "r"(addr));
}
__device__ __forceinline__ void ldmx2(uint32_t& r0, uint32_t& r1, uint32_t addr) {
    asm volatile("ldmatrix.sync.aligned.m8n8.x2.shared.b16 {%0,%1}, [%2];"
                 : "=r"(r0), "=r"(r1) : "r"(addr));
}
__device__ __forceinline__ void mma16816(float* c, const uint32_t* a, const uint32_t* b) {
    asm volatile(
        "mma.sync.aligned.m16n8k16.row.col.f32.bf16.bf16.f32 "
        "{%0,%1,%2,%3}, {%4,%5,%6,%7}, {%8,%9}, {%0,%1,%2,%3};"
        : "+f"(c[0]), "+f"(c[1]), "+f"(c[2]), "+f"(c[3])
        : "r"(a[0]), "r"(a[1]), "r"(a[2]), "r"(a[3]), "r"(b[0]), "r"(b[1]));
}

// ===========================================================================
// Split f32 -> (bf16 hi, bf16 lo)
// ===========================================================================
struct alignas(8) bf4 { __nv_bfloat16 a, b, c, d; };

__global__ void split_f32_kernel(const float* __restrict__ in,
                                 __nv_bfloat16* __restrict__ hi,
                                 __nv_bfloat16* __restrict__ lo, int n4) {
    int i = blockIdx.x * blockDim.x + threadIdx.x;
    int stride = gridDim.x * blockDim.x;
    for (; i < n4; i += stride) {
        float4 v = ((const float4*)in)[i];
        __nv_bfloat16 h0 = __float2bfloat16(v.x);
        __nv_bfloat16 h1 = __float2bfloat16(v.y);
        __nv_bfloat16 h2 = __float2bfloat16(v.z);
        __nv_bfloat16 h3 = __float2bfloat16(v.w);
        bf4 H = {h0, h1, h2, h3};
        bf4 L = {__float2bfloat16(v.x - __bfloat162float(h0)),
                 __float2bfloat16(v.y - __bfloat162float(h1)),
                 __float2bfloat16(v.z - __bfloat162float(h2)),
                 __float2bfloat16(v.w - __bfloat162float(h3))};
        ((bf4*)hi)[i] = H;
        ((bf4*)lo)[i] = L;
    }
}

// ===========================================================================
// Transpose + split: W [K][N] f32 -> W^T [N][K] bf16 hi/lo
// ===========================================================================
__global__ void transpose_split_kernel(const float* __restrict__ W,
                                       __nv_bfloat16* __restrict__ Thi,
                                       __nv_bfloat16* __restrict__ Tlo) {
    __shared__ float t[32][33];
    const int n0 = blockIdx.x << 5;
    const int k0 = blockIdx.y << 5;
    const int tx = threadIdx.x, ty = threadIdx.y;
#pragma unroll
    for (int j = 0; j < 4; j++)
        t[ty + (j << 3)][tx] = W[(k0 + ty + (j << 3)) * DIM + n0 + tx];
    __syncthreads();
#pragma unroll
    for (int j = 0; j < 4; j++) {
        float v = t[tx][ty + (j << 3)];
        __nv_bfloat16 h = __float2bfloat16(v);
        int o = (n0 + ty + (j << 3)) * DIM + k0 + tx;
        Thi[o] = h;
        Tlo[o] = __float2bfloat16(v - __bfloat162float(h));
    }
}

// ===========================================================================
// Tensor-core GEMM via mma.sync (split bf16, fp32 accum):
//   C[8192,1024] = (A @ W + bias) * scale ; A split row-major, W^T split [N][K]
// 128x128 CTA tile, BK=32, 8 warps (64x32 each), cp.async double buffer.
// smem row stride 40 elems (80B) -> conflict-free ldmatrix.
// ===========================================================================
#define GSTRIDE 40                       // elems per smem row (80 B)
#define GTILE_BYTES (128 * GSTRIDE * 2)  // 10240 B
#define GSTAGE_BYTES (4 * GTILE_BYTES)   // Ahi,Alo,Bhi,Blo = 40960 B
#define GSMEM_BYTES (2 * GSTAGE_BYTES)   // 81920 B

__global__ __launch_bounds__(256, 1)
void gemm_mma_kernel(const __nv_bfloat16* __restrict__ Ahi,
                     const __nv_bfloat16* __restrict__ Alo,
                     const __nv_bfloat16* __restrict__ Bhi,
                     const __nv_bfloat16* __restrict__ Blo,
                     const float* __restrict__ bias,
                     float* __restrict__ C, float scale) {
    extern __shared__ __align__(16) char smem[];
    const uint32_t sbase = smem_u32(smem);

    const int tid = threadIdx.x;
    const int wid = tid >> 5;
    const int lane = tid & 31;
    const int m0 = blockIdx.y << 7;
    const int n0 = blockIdx.x << 7;
    const int wm = (wid & 1) << 6;    // warp row offset (0/64)
    const int wn = (wid >> 1) << 5;   // warp col offset (0/32/64/96)

    const __nv_bfloat16* srcs[4] = {Ahi + m0 * 1024, Alo + m0 * 1024,
                                    Bhi + n0 * 1024, Blo + n0 * 1024};

    float acc[4][4][4];
#pragma unroll
    for (int a = 0; a < 4; a++)
#pragma unroll
        for (int b = 0; b < 4; b++)
#pragma unroll
            for (int c = 0; c < 4; c++) acc[a][b][c] = 0.f;

    // ldmatrix lane addressing
    const int a_r = lane & 15, a_k = lane >> 4;          // A: row, k-half
    const int b_r = lane & 7, b_k = (lane >> 3) & 1;     // B: row, k-half

    auto load_stage = [&](int kt, int buf) {
        const int kb = kt << 5;
        uint32_t sb = sbase + buf * GSTAGE_BYTES;
#pragma unroll
        for (int i = 0; i < 8; i++) {
            int tile = i >> 1;
            int idx = ((i & 1) << 8) + tid;
            int row = idx >> 2;
            int ch = idx & 3;
            const __nv_bfloat16* g = srcs[tile] + row * 1024 + kb + (ch << 3);
            uint32_t s = sb + tile * GTILE_BYTES + (row * GSTRIDE + (ch << 3)) * 2;
            CP_ASYNC16(s, g);
        }
    };

    load_stage(0, 0);
    CP_COMMIT();

    for (int kt = 0; kt < 32; kt++) {
        const int buf = kt & 1;
        if (kt + 1 < 32) {
            load_stage(kt + 1, buf ^ 1);
            CP_COMMIT();
            CP_WAIT(1);
        } else {
            CP_WAIT(0);
        }
        __syncthreads();

        const uint32_t sb = sbase + buf * GSTAGE_BYTES;
        const uint32_t sAhi = sb;
        const uint32_t sAlo = sb + GTILE_BYTES;
        const uint32_t sBhi = sb + 2 * GTILE_BYTES;
        const uint32_t sBlo = sb + 3 * GTILE_BYTES;

#pragma unroll
        for (int ks = 0; ks < 2; ks++) {
            uint32_t ah[4][4], al[4][4], bh[4][2], bl[4][2];
#pragma unroll
            for (int mt = 0; mt < 4; mt++) {
                uint32_t off = ((wm + (mt << 4) + a_r) * GSTRIDE + (ks << 4) + (a_k << 3)) * 2;
                ldmx4(ah[mt][0], ah[mt][1], ah[mt][2], ah[mt][3], sAhi + off);
                ldmx4(al[mt][0], al[mt][1], al[mt][2], al[mt][3], sAlo + off);
            }
#pragma unroll
            for (int nt = 0; nt < 4; nt++) {
                uint32_t off = ((wn + (nt << 3) + b_r) * GSTRIDE + (ks << 4) + (b_k << 3)) * 2;
                ldmx2(bh[nt][0], bh[nt][1], sBhi + off);
                ldmx2(bl[nt][0], bl[nt][1], sBlo + off);
            }
#pragma unroll
            for (int mt = 0; mt < 4; mt++)
#pragma unroll
                for (int nt = 0; nt < 4; nt++) {
                    mma16816(acc[mt][nt], ah[mt], bh[nt]);
                    mma16816(acc[mt][nt], al[mt], bh[nt]);
                    mma16816(acc[mt][nt], ah[mt], bl[nt]);
                }
        }
        __syncthreads();
    }

    // Epilogue: direct fp32 stores with fused bias+scale
    const int er = lane >> 2;            // 0..7
    const int ec = (lane & 3) << 1;      // 0,2,4,6
#pragma unroll
    for (int mt = 0; mt < 4; mt++) {
#pragma unroll
        for (int nt = 0; nt < 4; nt++) {
            int row = m0 + wm + (mt << 4) + er;
            int col = n0 + wn + (nt << 3) + ec;
            float2 b2 = *(const float2*)(bias + col);
            float2 o0, o1;
            o0.x = (acc[mt][nt][0] + b2.x) * scale;
            o0.y = (acc[mt][nt][1] + b2.y) * scale;
            o1.x = (acc[mt][nt][2] + b2.x) * scale;
            o1.y = (acc[mt][nt][3] + b2.y) * scale;
            *(float2*)(C + row * 1024 + col) = o0;
            *(float2*)(C + (row + 8) * 1024 + col) = o1;
        }
    }
}

// ===========================================================================
// Fused attention per group g=(b,h) — SIMT fp32 (round-1 version, passing).
// ===========================================================================
#define ATT_S_FLOATS   (32 * 1024)
#define ATT_Q_FLOATS   (64 * 32)
#define ATT_KV_FLOATS  (128 * 68)
#define ATT_SMEM_BYTES ((ATT_S_FLOATS + ATT_Q_FLOATS + ATT_KV_FLOATS) * 4)

__global__ __launch_bounds__(256, 1)
void attn_kernel() {
    extern __shared__ float sm[];
    float* S  = sm;
    float* Qt = sm + ATT_S_FLOATS;
    float* KV = Qt + ATT_Q_FLOATS;

    const int g  = blockIdx.y;
    const int qt = blockIdx.x;
    const int b  = g >> 4;
    const int h  = g & 15;
    const int base = (b << 20) + ((h << 6) << 10);
    const float* Qb = g_Q + base;
    const float* Kb = g_K + base;
    const float* Vb = g_V + base;
    const int tid = threadIdx.x;

#pragma unroll
    for (int i = 0; i < 2; i++) {
        int q = tid + (i << 8);
        int d = q >> 3, c4 = q & 7;
        float4 v = *(const float4*)(Qb + d * 1024 + (qt << 5) + (c4 << 2));
        *(float4*)(&Qt[d * 32 + (c4 << 2)]) = v;
    }

    {
        const int ty = tid >> 5;
        const int tx = tid & 31;
        for (int kc = 0; kc < 8; kc++) {
#pragma unroll
            for (int i = 0; i < 8; i++) {
                int q = tid + (i << 8);
                int d = q >> 5, c4 = q & 31;
                *(float4*)(&KV[d * 128 + (c4 << 2)]) =
                    *(const float4*)(Kb + d * 1024 + (kc << 7) + (c4 << 2));
            }
            __syncthreads();

            float acc[4][4];
#pragma unroll
            for (int i = 0; i < 4; i++)
#pragma unroll
                for (int j = 0; j < 4; j++) acc[i][j] = 0.f;

#pragma unroll 8
            for (int d = 0; d < 64; d++) {
                float4 a = *(const float4*)(&Qt[d * 32 + (ty << 2)]);
                float4 k4 = *(const float4*)(&KV[d * 128 + (tx << 2)]);
                float av[4] = {a.x, a.y, a.z, a.w};
                float kv[4] = {k4.x, k4.y, k4.z, k4.w};
#pragma unroll
                for (int i = 0; i < 4; i++)
#pragma unroll
                    for (int j = 0; j < 4; j++) acc[i][j] += av[i] * kv[j];
            }
#pragma unroll
            for (int i = 0; i < 4; i++) {
                *(float4*)(&S[((ty << 2) + i) * 1024 + (kc << 7) + (tx << 2)]) =
                    make_float4(acc[i][0], acc[i][1], acc[i][2], acc[i][3]);
            }
            __syncthreads();
        }
    }

    {
        const int w = tid >> 5, lane = tid & 31;
#pragma unroll
        for (int rr = 0; rr < 4; rr++) {
            float* row = S + ((w << 2) + rr) * 1024;
            float m = -1e30f;
            for (int c = lane; c < 1024; c += 32) m = fmaxf(m, row[c]);
#pragma unroll
            for (int o = 16; o > 0; o >>= 1) m = fmaxf(m, __shfl_xor_sync(0xffffffffu, m, o));
            float s = 0.f;
            for (int c = lane; c < 1024; c += 32) {
                float e = __expf(row[c] - m);
                row[c] = e;
                s += e;
            }
#pragma unroll
            for (int o = 16; o > 0; o >>= 1) s += __shfl_xor_sync(0xffffffffu, s, o);
            float inv = 1.0f / s;
            for (int c = lane; c < 1024; c += 32) row[c] *= inv;
        }
    }
    __syncthreads();

    {
        const int ty2 = tid >> 4;
        const int tx2 = tid & 15;
        float acc[2][4];
#pragma unroll
        for (int i = 0; i < 2; i++)
#pragma unroll
            for (int j = 0; j < 4; j++) acc[i][j] = 0.f;

        for (int kc = 0; kc < 8; kc++) {
#pragma unroll
            for (int i = 0; i < 8; i++) {
                int q = tid + (i << 8);
                int t2 = q & 127;
                int d0 = (q >> 7) << 2;
                float4 v;
                v.x = Vb[(d0 + 0) * 1024 + (kc << 7) + t2];
                v.y = Vb[(d0 + 1) * 1024 + (kc << 7) + t2];
                v.z = Vb[(d0 + 2) * 1024 + (kc << 7) + t2];
                v.w = Vb[(d0 + 3) * 1024 + (kc << 7) + t2];
                *(float4*)(&KV[t2 * 68 + d0]) = v;
            }
            __syncthreads();

            const float* Srow0 = S + (ty2 << 1) * 1024 + (kc << 7);
            const float* Srow1 = Srow0 + 1024;
#pragma unroll 4
            for (int t2 = 0; t2 < 128; t2 += 4) {
                float4 s0 = *(const float4*)(Srow0 + t2);
                float4 s1 = *(const float4*)(Srow1 + t2);
                float s0a[4] = {s0.x, s0.y, s0.z, s0.w};
                float s1a[4] = {s1.x, s1.y, s1.z, s1.w};
#pragma unroll
                for (int u = 0; u < 4; u++) {
                    float4 v = *(const float4*)(&KV[(t2 + u) * 68 + (tx2 << 2)]);
                    float vv[4] = {v.x, v.y, v.z, v.w};
#pragma unroll
                    for (int j = 0; j < 4; j++) {
                        acc[0][j] += s0a[u] * vv[j];
                        acc[1][j] += s1a[u] * vv[j];
                    }
                }
            }
            __syncthreads();
        }

#pragma unroll
        for (int i = 0; i < 2; i++) {
            int t1 = (qt << 5) + (ty2 << 1) + i;
            int p = t1 >> 4, qq = t1 & 15;
            float* dst = g_A + (b << 20) + ((h << 6) + p) * 1024 + (qq << 6) + (tx2 << 2);
            *(float4*)dst = make_float4(acc[i][0], acc[i][1], acc[i][2], acc[i][3]);
        }
    }
}

// ===========================================================================
extern "C" void kernel_launch(void* const* d_in, const int* in_sizes, int n_in,
                              void* d_out, int out_size) {
    const float* x  = (const float*)d_in[0];
    const float* Wq = (const float*)d_in[1];
    const float* bq = (const float*)d_in[2];
    const float* Wk = (const float*)d_in[3];
    const float* bk = (const float*)d_in[4];
    const float* Wv = (const float*)d_in[5];
    const float* bv = (const float*)d_in[6];
    const float* Wo = (const float*)d_in[7];
    const float* bo = (const float*)d_in[8];
    float* out = (float*)d_out;

    float *Qp, *Kp, *Vp, *Ap;
    cudaGetSymbolAddress((void**)&Qp, g_Q);
    cudaGetSymbolAddress((void**)&Kp, g_K);
    cudaGetSymbolAddress((void**)&Vp, g_V);
    cudaGetSymbolAddress((void**)&Ap, g_A);
    __nv_bfloat16 *xhi, *xlo, *ahi, *alo, *whi, *wlo;
    cudaGetSymbolAddress((void**)&xhi, g_xhi);
    cudaGetSymbolAddress((void**)&xlo, g_xlo);
    cudaGetSymbolAddress((void**)&ahi, g_ahi);
    cudaGetSymbolAddress((void**)&alo, g_alo);
    cudaGetSymbolAddress((void**)&whi, g_wt_hi);
    cudaGetSymbolAddress((void**)&wlo, g_wt_lo);

    cudaFuncSetAttribute(attn_kernel, cudaFuncAttributeMaxDynamicSharedMemorySize,
                         ATT_SMEM_BYTES);
    cudaFuncSetAttribute(gemm_mma_kernel, cudaFuncAttributeMaxDynamicSharedMemorySize,
                         GSMEM_BYTES);

    // 1) Split x into bf16 hi/lo
    split_f32_kernel<<<2048, 256>>>(x, xhi, xlo, BLN * DIM / 4);

    // 2) Transpose+split weights (W^T [n][k])
    dim3 tgrid(32, 32), tblk(32, 8);
    transpose_split_kernel<<<tgrid, tblk>>>(Wq, whi + 0 * DIM * DIM, wlo + 0 * DIM * DIM);
    transpose_split_kernel<<<tgrid, tblk>>>(Wk, whi + 1 * DIM * DIM, wlo + 1 * DIM * DIM);
    transpose_split_kernel<<<tgrid, tblk>>>(Wv, whi + 2 * DIM * DIM, wlo + 2 * DIM * DIM);
    transpose_split_kernel<<<tgrid, tblk>>>(Wo, whi + 3 * DIM * DIM, wlo + 3 * DIM * DIM);

    // 3) QKV projections on tensor cores (mma.sync)
    dim3 ggrid(8, 64);
    gemm_mma_kernel<<<ggrid, 256, GSMEM_BYTES>>>(xhi, xlo, whi + 0 * DIM * DIM,
                                                 wlo + 0 * DIM * DIM, bq, Qp, QKSCALE);
    gemm_mma_kernel<<<ggrid, 256, GSMEM_BYTES>>>(xhi, xlo, whi + 1 * DIM * DIM,
                                                 wlo + 1 * DIM * DIM, bk, Kp, QKSCALE);
    gemm_mma_kernel<<<ggrid, 256, GSMEM_BYTES>>>(xhi, xlo, whi + 2 * DIM * DIM,
                                                 wlo + 2 * DIM * DIM, bv, Vp, 1.0f);

    // 4) Attention (SIMT fp32, exact softmax)
    attn_kernel<<<dim3(32, 128), 256, ATT_SMEM_BYTES>>>();

    // 5) Output projection
    split_f32_kernel<<<2048, 256>>>(Ap, ahi, alo, BLN * DIM / 4);
    gemm_mma_kernel<<<ggrid, 256, GSMEM_BYTES>>>(ahi, alo, whi + 3 * DIM * DIM,
                                                 wlo + 3 * DIM * DIM, bo, out, 1.0f);
}

// round 5
// speedup vs baseline: 1.9268x; 1.3797x over previous
#include <cuda_runtime.h>
#include <cuda_bf16.h>
#include <cstdint>

// ===========================================================================
// Problem constants
// ===========================================================================
#define BLN 8192          // B*L
#define DIM 1024          // D
#define QKSCALE 0.03125f  // 1/sqrt(1024)

// ===========================================================================
// Device scratch (allocation-free rule: device globals)
// ===========================================================================
__device__ __nv_bfloat16 g_xhi[BLN * DIM];
__device__ __nv_bfloat16 g_xlo[BLN * DIM];
__device__ __nv_bfloat16 g_wt_hi[4][DIM * DIM];   // W^T [n][k] hi
__device__ __nv_bfloat16 g_wt_lo[4][DIM * DIM];   // W^T [n][k] lo
// Batch-transposed split Q,K: [b][ch][l]  (ch = attention row/col index)
__device__ __nv_bfloat16 g_QThi[BLN * DIM];
__device__ __nv_bfloat16 g_QTlo[BLN * DIM];
__device__ __nv_bfloat16 g_KThi[BLN * DIM];
__device__ __nv_bfloat16 g_KTlo[BLN * DIM];
// Natural split V and attention output A: [row=(b,l)][ch]
__device__ __nv_bfloat16 g_Vhi[BLN * DIM];
__device__ __nv_bfloat16 g_Vlo[BLN * DIM];
__device__ __nv_bfloat16 g_Ahi[BLN * DIM];
__device__ __nv_bfloat16 g_Alo[BLN * DIM];

// ===========================================================================
// PTX helpers (sm_80-era: target is plain sm_100, tcgen05 unavailable)
// ===========================================================================
__device__ __forceinline__ uint32_t smem_u32(const void* p) {
    uint32_t a;
    asm("{ .reg .u64 t; cvta.to.shared.u64 t, %1; cvt.u32.u64 %0, t; }" : "=r"(a) : "l"(p));
    return a;
}
#define CP_ASYNC16(saddr, gptr) \
    asm volatile("cp.async.cg.shared.global [%0], [%1], 16;" :: "r"(saddr), "l"(gptr))
#define CP_COMMIT() asm volatile("cp.async.commit_group;" ::: "memory")
#define CP_WAIT(n)  asm volatile("cp.async.wait_group %0;" :: "n"(n) : "memory")

__device__ __forceinline__ void ldmx4(uint32_t& r0, uint32_t& r1, uint32_t& r2, uint32_t& r3,
                                      uint32_t addr) {
    asm volatile("ldmatrix.sync.aligned.m8n8.x4.shared.b16 {%0,%1,%2,%3}, [%4];"
                 : "=r"(r0), "=r"(r1), "=r"(r2), "=r"(r3) : "r"(addr));
}
__device__ __forceinline__ void ldmx2(uint32_t& r0, uint32_t& r1, uint32_t addr) {
    asm volatile("ldmatrix.sync.aligned.m8n8.x2.shared.b16 {%0,%1}, [%2];"
                 : "=r"(r0), "=r"(r1) : "r"(addr));
}
__device__ __forceinline__ void mma16816(float* c, const uint32_t* a, const uint32_t* b) {
    asm volatile(
        "mma.sync.aligned.m16n8k16.row.col.f32.bf16.bf16.f32 "
        "{%0,%1,%2,%3}, {%4,%5,%6,%7}, {%8,%9}, {%0,%1,%2,%3};"
        : "+f"(c[0]), "+f"(c[1]), "+f"(c[2]), "+f"(c[3])
        : "r"(a[0]), "r"(a[1]), "r"(a[2]), "r"(a[3]), "r"(b[0]), "r"(b[1]));
}

// ===========================================================================
// Split f32 -> (bf16 hi, bf16 lo)
// ===========================================================================
struct alignas(8) bf4 { __nv_bfloat16 a, b, c, d; };

__global__ void split_f32_kernel(const float* __restrict__ in,
                                 __nv_bfloat16* __restrict__ hi,
                                 __nv_bfloat16* __restrict__ lo, int n4) {
    int i = blockIdx.x * blockDim.x + threadIdx.x;
    int stride = gridDim.x * blockDim.x;
    for (; i < n4; i += stride) {
        float4 v = ((const float4*)in)[i];
        __nv_bfloat16 h0 = __float2bfloat16(v.x);
        __nv_bfloat16 h1 = __float2bfloat16(v.y);
        __nv_bfloat16 h2 = __float2bfloat16(v.z);
        __nv_bfloat16 h3 = __float2bfloat16(v.w);
        bf4 H = {h0, h1, h2, h3};
        bf4 L = {__float2bfloat16(v.x - __bfloat162float(h0)),
                 __float2bfloat16(v.y - __bfloat162float(h1)),
                 __float2bfloat16(v.z - __bfloat162float(h2)),
                 __float2bfloat16(v.w - __bfloat162float(h3))};
        ((bf4*)hi)[i] = H;
        ((bf4*)lo)[i] = L;
    }
}

// ===========================================================================
// Transpose + split: W [K][N] f32 -> W^T [N][K] bf16 hi/lo
// ===========================================================================
__global__ void transpose_split_kernel(const float* __restrict__ W,
                                       __nv_bfloat16* __restrict__ Thi,
                                       __nv_bfloat16* __restrict__ Tlo) {
    __shared__ float t[32][33];
    const int n0 = blockIdx.x << 5;
    const int k0 = blockIdx.y << 5;
    const int tx = threadIdx.x, ty = threadIdx.y;
#pragma unroll
    for (int j = 0; j < 4; j++)
        t[ty + (j << 3)][tx] = W[(k0 + ty + (j << 3)) * DIM + n0 + tx];
    __syncthreads();
#pragma unroll
    for (int j = 0; j < 4; j++) {
        float v = t[tx][ty + (j << 3)];
        __nv_bfloat16 h = __float2bfloat16(v);
        int o = (n0 + ty + (j << 3)) * DIM + k0 + tx;
        Thi[o] = h;
        Tlo[o] = __float2bfloat16(v - __bfloat162float(h));
    }
}

// ===========================================================================
// Tensor-core GEMM via mma.sync (split bf16, fp32 accum):
//   C = (A @ W + bias) * scale
// modes: 0 = fp32 natural write (Cf)
//        1 = split-bf16 natural write (Chi/Clo)        [V]
//        2 = split-bf16 batch-transposed write [b][ch][l] (Chi/Clo)  [Q, K]
// ===========================================================================
#define GSTRIDE 40
#define GTILE_BYTES (128 * GSTRIDE * 2)
#define GSTAGE_BYTES (4 * GTILE_BYTES)
#define GSMEM_BYTES (2 * GSTAGE_BYTES)   // 81920 B (>= 69632 for mode-2 staging)

__global__ __launch_bounds__(256, 1)
void gemm_mma_kernel(const __nv_bfloat16* __restrict__ Ahi,
                     const __nv_bfloat16* __restrict__ Alo,
                     const __nv_bfloat16* __restrict__ Bhi,
                     const __nv_bfloat16* __restrict__ Blo,
                     const float* __restrict__ bias,
                     float* __restrict__ Cf,
                     __nv_bfloat16* __restrict__ Chi,
                     __nv_bfloat16* __restrict__ Clo,
                     float scale, int mode) {
    extern __shared__ __align__(16) char smem[];
    const uint32_t sbase = smem_u32(smem);

    const int tid = threadIdx.x;
    const int wid = tid >> 5;
    const int lane = tid & 31;
    const int m0 = blockIdx.y << 7;
    const int n0 = blockIdx.x << 7;
    const int wm = (wid & 1) << 6;
    const int wn = (wid >> 1) << 5;

    const __nv_bfloat16* srcs[4] = {Ahi + m0 * 1024, Alo + m0 * 1024,
                                    Bhi + n0 * 1024, Blo + n0 * 1024};

    float acc[4][4][4];
#pragma unroll
    for (int a = 0; a < 4; a++)
#pragma unroll
        for (int b = 0; b < 4; b++)
#pragma unroll
            for (int c = 0; c < 4; c++) acc[a][b][c] = 0.f;

    const int a_r = lane & 15, a_k = lane >> 4;
    const int b_r = lane & 7, b_k = (lane >> 3) & 1;

    auto load_stage = [&](int kt, int buf) {
        const int kb = kt << 5;
        uint32_t sb = sbase + buf * GSTAGE_BYTES;
#pragma unroll
        for (int i = 0; i < 8; i++) {
            int tile = i >> 1;
            int idx = ((i & 1) << 8) + tid;
            int row = idx >> 2;
            int ch = idx & 3;
            const __nv_bfloat16* g = srcs[tile] + row * 1024 + kb + (ch << 3);
            uint32_t s = sb + tile * GTILE_BYTES + (row * GSTRIDE + (ch << 3)) * 2;
            CP_ASYNC16(s, g);
        }
    };

    load_stage(0, 0);
    CP_COMMIT();

    for (int kt = 0; kt < 32; kt++) {
        const int buf = kt & 1;
        if (kt + 1 < 32) {
            load_stage(kt + 1, buf ^ 1);
            CP_COMMIT();
            CP_WAIT(1);
        } else {
            CP_WAIT(0);
        }
        __syncthreads();

        const uint32_t sb = sbase + buf * GSTAGE_BYTES;
        const uint32_t sAhi = sb;
        const uint32_t sAlo = sb + GTILE_BYTES;
        const uint32_t sBhi = sb + 2 * GTILE_BYTES;
        const uint32_t sBlo = sb + 3 * GTILE_BYTES;

#pragma unroll
        for (int ks = 0; ks < 2; ks++) {
            uint32_t ah[4][4], al[4][4], bh[4][2], bl[4][2];
#pragma unroll
            for (int mt = 0; mt < 4; mt++) {
                uint32_t off = ((wm + (mt << 4) + a_r) * GSTRIDE + (ks << 4) + (a_k << 3)) * 2;
                ldmx4(ah[mt][0], ah[mt][1], ah[mt][2], ah[mt][3], sAhi + off);
                ldmx4(al[mt][0], al[mt][1], al[mt][2], al[mt][3], sAlo + off);
            }
#pragma unroll
            for (int nt = 0; nt < 4; nt++) {
                uint32_t off = ((wn + (nt << 3) + b_r) * GSTRIDE + (ks << 4) + (b_k << 3)) * 2;
                ldmx2(bh[nt][0], bh[nt][1], sBhi + off);
                ldmx2(bl[nt][0], bl[nt][1], sBlo + off);
            }
#pragma unroll
            for (int mt = 0; mt < 4; mt++)
#pragma unroll
                for (int nt = 0; nt < 4; nt++) {
                    mma16816(acc[mt][nt], ah[mt], bh[nt]);
                    mma16816(acc[mt][nt], al[mt], bh[nt]);
                    mma16816(acc[mt][nt], ah[mt], bl[nt]);
                }
        }
        __syncthreads();
    }

    const int er = lane >> 2;
    const int ec = (lane & 3) << 1;

    if (mode == 0) {
        // fp32 natural
#pragma unroll
        for (int mt = 0; mt < 4; mt++) {
#pragma unroll
            for (int nt = 0; nt < 4; nt++) {
                int row = m0 + wm + (mt << 4) + er;
                int col = n0 + wn + (nt << 3) + ec;
                float2 b2 = *(const float2*)(bias + col);
                float2 o0, o1;
                o0.x = (acc[mt][nt][0] + b2.x) * scale;
                o0.y = (acc[mt][nt][1] + b2.y) * scale;
                o1.x = (acc[mt][nt][2] + b2.x) * scale;
                o1.y = (acc[mt][nt][3] + b2.y) * scale;
                *(float2*)(Cf + row * 1024 + col) = o0;
                *(float2*)(Cf + (row + 8) * 1024 + col) = o1;
            }
        }
    } else if (mode == 1) {
        // split bf16 natural (V)
#pragma unroll
        for (int mt = 0; mt < 4; mt++) {
#pragma unroll
            for (int nt = 0; nt < 4; nt++) {
                int row = m0 + wm + (mt << 4) + er;
                int col = n0 + wn + (nt << 3) + ec;
                float2 b2 = *(const float2*)(bias + col);
#pragma unroll
                for (int half = 0; half < 2; half++) {
                    int r = row + half * 8;
                    float v0 = (acc[mt][nt][half * 2 + 0] + b2.x) * scale;
                    float v1 = (acc[mt][nt][half * 2 + 1] + b2.y) * scale;
                    __nv_bfloat16 h0 = __float2bfloat16(v0);
                    __nv_bfloat16 h1 = __float2bfloat16(v1);
                    __nv_bfloat162 hp; hp.x = h0; hp.y = h1;
                    *(__nv_bfloat162*)(Chi + r * 1024 + col) = hp;
                    __nv_bfloat162 lp;
                    lp.x = __float2bfloat16(v0 - __bfloat162float(h0));
                    lp.y = __float2bfloat16(v1 - __bfloat162float(h1));
                    *(__nv_bfloat162*)(Clo + r * 1024 + col) = lp;
                }
            }
        }
    } else {
        // mode 2: transposed split write through smem staging [n][m]
        __nv_bfloat16* sthi = (__nv_bfloat16*)smem;
        __nv_bfloat16* stlo = (__nv_bfloat16*)(smem + 34816);
#pragma unroll
        for (int mt = 0; mt < 4; mt++) {
#pragma unroll
            for (int nt = 0; nt < 4; nt++) {
                int mrow = wm + (mt << 4) + er;     // local 0..127
                int ncol = wn + (nt << 3) + ec;     // local 0..127
                float2 b2 = *(const float2*)(bias + n0 + ncol);
#pragma unroll
                for (int half = 0; half < 2; half++) {
                    int r = mrow + half * 8;
                    float v0 = (acc[mt][nt][half * 2 + 0] + b2.x) * scale;
                    float v1 = (acc[mt][nt][half * 2 + 1] + b2.y) * scale;
                    __nv_bfloat16 h0 = __float2bfloat16(v0);
                    __nv_bfloat16 h1 = __float2bfloat16(v1);
                    sthi[ncol * 136 + r] = h0;
                    sthi[(ncol + 1) * 136 + r] = h1;
                    stlo[ncol * 136 + r] = __float2bfloat16(v0 - __bfloat162float(h0));
                    stlo[(ncol + 1) * 136 + r] = __float2bfloat16(v1 - __bfloat162float(h1));
                }
            }
        }
        __syncthreads();
        const int bidx = m0 >> 10;
        const int l0 = m0 & 1023;
#pragma unroll
        for (int i = 0; i < 16; i++) {
            int q = tid + (i << 8);           // 0..4095
            int t = q >> 11;                  // 0:hi 1:lo
            int idx = q & 2047;
            int nrow = idx >> 4;              // 0..127 (ch local)
            int ch = idx & 15;                // 16B chunk within the 128-l row
            uint4 v = *(const uint4*)(smem + t * 34816 + (nrow * 136 + ch * 8) * 2);
            __nv_bfloat16* dst = (t ? Clo : Chi) +
                bidx * 1048576 + (n0 + nrow) * 1024 + l0 + ch * 8;
            *(uint4*)dst = v;
        }
    }
}

// ===========================================================================
// Attention with mma.sync, exact softmax.
// CTA = (group g=(b,h), t1 block of 32).  S[32][1024] fp32 in smem.
// Phase1: S = Q^T K  (A = QT[b][t1][h*64+d], B = KT[b][t2][h*64+d])
// Phase2: O = P V    (A = P split bf16,     B = V natural [l][ch])
// Both 3-term split.  Output written as split bf16 to g_Ahi/g_Alo.
// ===========================================================================
#define AS_STRIDE 1032
#define ATT_R_OFF 132096                      // after S (32*1032*4)
#define ATT_SMEM  219136

__global__ __launch_bounds__(256, 1)
void attn_mma_kernel() {
    extern __shared__ __align__(16) char sm[];
    float* S = (float*)sm;
    const uint32_t sb = smem_u32(sm);
    const uint32_t R = sb + ATT_R_OFF;

    const int g = blockIdx.y, qt = blockIdx.x;
    const int b = g >> 4, h = g & 15;
    const int tid = threadIdx.x, wid = tid >> 5, lane = tid & 31;

    const int qkbase = b * 1048576 + h * 64;

    const int a_r = lane & 15, a_k = lane >> 4;
    const int b_r = lane & 7, b_k = (lane >> 3) & 1;
    const int er = lane >> 2, ec = (lane & 3) << 1;

    // ---- Phase 1 loads: Q tile (once) + K chunk 0 ----
    {
#pragma unroll
        for (int i = 0; i < 2; i++) {
            int q = tid + (i << 8);           // 0..511
            int t = q >> 8, idx = q & 255;
            int r = idx >> 3, ch = idx & 7;
            const __nv_bfloat16* src =
                (t ? g_QTlo : g_QThi) + qkbase + (qt * 32 + r) * 1024 + ch * 8;
            uint32_t dst = R + t * 4608 + (r * 72 + ch * 8) * 2;
            CP_ASYNC16(dst, src);
        }
    }
    auto load_K = [&](int c, int buf) {
        int base = qkbase + c * 128 * 1024;
#pragma unroll
        for (int i = 0; i < 8; i++) {
            int q = tid + (i << 8);           // 0..2047
            int t = q >> 10, idx = q & 1023;
            int r = idx >> 3, ch = idx & 7;
            const __nv_bfloat16* src = (t ? g_KTlo : g_KThi) + base + r * 1024 + ch * 8;
            uint32_t dst = R + 9216 + buf * 36864 + t * 18432 + (r * 72 + ch * 8) * 2;
            CP_ASYNC16(dst, src);
        }
    };
    load_K(0, 0);
    CP_COMMIT();

    uint32_t qh[2][4][4], ql[2][4][4];

    for (int c = 0; c < 8; c++) {
        const int buf = c & 1;
        __syncthreads();                       // prior chunk's mma done (buffer reuse)
        if (c + 1 < 8) {
            load_K(c + 1, buf ^ 1);
            CP_COMMIT();
            CP_WAIT(1);
        } else {
            CP_WAIT(0);
        }
        __syncthreads();
        if (c == 0) {
            // hoist Q fragments (reused for all chunks)
#pragma unroll
            for (int mt = 0; mt < 2; mt++)
#pragma unroll
                for (int ks = 0; ks < 4; ks++) {
                    uint32_t off = ((mt * 16 + a_r) * 72 + ks * 16 + a_k * 8) * 2;
                    ldmx4(qh[mt][ks][0], qh[mt][ks][1], qh[mt][ks][2], qh[mt][ks][3], R + off);
                    ldmx4(ql[mt][ks][0], ql[mt][ks][1], ql[mt][ks][2], ql[mt][ks][3],
                          R + 4608 + off);
                }
        }
        float acc[2][2][4];
#pragma unroll
        for (int i = 0; i < 2; i++)
#pragma unroll
            for (int j = 0; j < 2; j++)
#pragma unroll
                for (int k = 0; k < 4; k++) acc[i][j][k] = 0.f;

        uint32_t kb = R + 9216 + buf * 36864;
#pragma unroll
        for (int ks = 0; ks < 4; ks++) {
            uint32_t bh[2][2], bl[2][2];
#pragma unroll
            for (int nt = 0; nt < 2; nt++) {
                uint32_t off = ((wid * 16 + nt * 8 + b_r) * 72 + ks * 16 + b_k * 8) * 2;
                ldmx2(bh[nt][0], bh[nt][1], kb + off);
                ldmx2(bl[nt][0], bl[nt][1], kb + 18432 + off);
            }
#pragma unroll
            for (int mt = 0; mt < 2; mt++)
#pragma unroll
                for (int nt = 0; nt < 2; nt++) {
                    mma16816(acc[mt][nt], qh[mt][ks], bh[nt]);
                    mma16816(acc[mt][nt], ql[mt][ks], bh[nt]);
                    mma16816(acc[mt][nt], qh[mt][ks], bl[nt]);
                }
        }
        // store S chunk
#pragma unroll
        for (int mt = 0; mt < 2; mt++)
#pragma unroll
            for (int nt = 0; nt < 2; nt++) {
                int row = mt * 16 + er;
                int col = c * 128 + wid * 16 + nt * 8 + ec;
                *(float2*)&S[row * AS_STRIDE + col] =
                    make_float2(acc[mt][nt][0], acc[mt][nt][1]);
                *(float2*)&S[(row + 8) * AS_STRIDE + col] =
                    make_float2(acc[mt][nt][2], acc[mt][nt][3]);
            }
    }
    __syncthreads();

    // ---- prefetch V0 (K buffers now free), then softmax ----
    auto load_V = [&](int c, int buf) {
#pragma unroll
        for (int i = 0; i < 8; i++) {
            int q = tid + (i << 8);           // 0..2047
            int t = q >> 10, idx = q & 1023;
            int r = idx >> 4, ch = idx & 15;  // 64 rows x 16 chunks
            const __nv_bfloat16* src =
                (t ? g_Vlo : g_Vhi) + (b * 1024 + h * 64 + r) * 1024 + c * 128 + ch * 8;
            uint32_t dst = R + 17408 + buf * 34816 + t * 17408 + (r * 136 + ch * 8) * 2;
            CP_ASYNC16(dst, src);
        }
    };
    load_V(0, 0);
    CP_COMMIT();

    // softmax: warp w -> rows 4w..4w+3
    {
#pragma unroll
        for (int rr = 0; rr < 4; rr++) {
            float* row = S + (wid * 4 + rr) * AS_STRIDE;
            float m = -1e30f;
            for (int cc = lane; cc < 1024; cc += 32) m = fmaxf(m, row[cc]);
#pragma unroll
            for (int o = 16; o > 0; o >>= 1) m = fmaxf(m, __shfl_xor_sync(0xffffffffu, m, o));
            float s = 0.f;
            for (int cc = lane; cc < 1024; cc += 32) {
                float e = __expf(row[cc] - m);
                row[cc] = e;
                s += e;
            }
#pragma unroll
            for (int o = 16; o > 0; o >>= 1) s += __shfl_xor_sync(0xffffffffu, s, o);
            float inv = 1.0f / s;
            for (int cc = lane; cc < 1024; cc += 32) row[cc] *= inv;
        }
    }
    __syncthreads();

    __nv_bfloat16* Ph = (__nv_bfloat16*)(sm + ATT_R_OFF);
    __nv_bfloat16* Pl = (__nv_bfloat16*)(sm + ATT_R_OFF + 8704);

    float oacc[2][4];
#pragma unroll
    for (int i = 0; i < 2; i++)
#pragma unroll
        for (int j = 0; j < 4; j++) oacc[i][j] = 0.f;

    for (int c = 0; c < 8; c++) {
        const int buf = c & 1;
        __syncthreads();                       // prior mma done (P + V buffer reuse)
        if (c + 1 < 8) {
            load_V(c + 1, buf ^ 1);
            CP_COMMIT();
        }
        // convert P chunk (overlaps V load latency)
        {
            int r = tid >> 3, c0 = (tid & 7) * 16;
            const float* srow = S + r * AS_STRIDE + c * 128 + c0;
            __nv_bfloat16* phr = Ph + r * 136 + c0;
            __nv_bfloat16* plr = Pl + r * 136 + c0;
#pragma unroll
            for (int j = 0; j < 16; j++) {
                float v = srow[j];
                __nv_bfloat16 hh = __float2bfloat16(v);
                phr[j] = hh;
                plr[j] = __float2bfloat16(v - __bfloat162float(hh));
            }
        }
        if (c + 1 < 8) CP_WAIT(1); else CP_WAIT(0);
        __syncthreads();

        uint32_t vb = R + 17408 + buf * 34816;
#pragma unroll
        for (int ks = 0; ks < 8; ks++) {
            uint32_t ph[2][4], pl[2][4], vh[2], vl[2];
#pragma unroll
            for (int mt = 0; mt < 2; mt++) {
                uint32_t off = R + ((mt * 16 + a_r) * 136 + ks * 16 + a_k * 8) * 2;
                ldmx4(ph[mt][0], ph[mt][1], ph[mt][2], ph[mt][3], off);
                ldmx4(pl[mt][0], pl[mt][1], pl[mt][2], pl[mt][3], off + 8704);
            }
            uint32_t voff = vb + ((wid * 8 + b_r) * 136 + ks * 16 + b_k * 8) * 2;
            ldmx2(vh[0], vh[1], voff);
            ldmx2(vl[0], vl[1], voff + 17408);
#pragma unroll
            for (int mt = 0; mt < 2; mt++) {
                mma16816(oacc[mt], ph[mt], vh);
                mma16816(oacc[mt], pl[mt], vh);
                mma16816(oacc[mt], ph[mt], vl);
            }
        }
    }

    // ---- write O as split bf16 to g_Ahi/g_Alo (reference scatter) ----
#pragma unroll
    for (int mt = 0; mt < 2; mt++) {
#pragma unroll
        for (int half = 0; half < 2; half++) {
            int t1 = qt * 32 + mt * 16 + er + half * 8;
            int p = t1 >> 4, qq = t1 & 15;
            int col = wid * 8 + ec;
            int off = (b * 1024 + h * 64 + p) * 1024 + qq * 64 + col;
            float v0 = oacc[mt][half * 2 + 0];
            float v1 = oacc[mt][half * 2 + 1];
            __nv_bfloat16 h0 = __float2bfloat16(v0);
            __nv_bfloat16 h1 = __float2bfloat16(v1);
            __nv_bfloat162 hp; hp.x = h0; hp.y = h1;
            *(__nv_bfloat162*)(g_Ahi + off) = hp;
            __nv_bfloat162 lp;
            lp.x = __float2bfloat16(v0 - __bfloat162float(h0));
            lp.y = __float2bfloat16(v1 - __bfloat162float(h1));
            *(__nv_bfloat162*)(g_Alo + off) = lp;
        }
    }
}

// ===========================================================================
extern "C" void kernel_launch(void* const* d_in, const int* in_sizes, int n_in,
                              void* d_out, int out_size) {
    const float* x  = (const float*)d_in[0];
    const float* Wq = (const float*)d_in[1];
    const float* bq = (const float*)d_in[2];
    const float* Wk = (const float*)d_in[3];
    const float* bk = (const float*)d_in[4];
    const float* Wv = (const float*)d_in[5];
    const float* bv = (const float*)d_in[6];
    const float* Wo = (const float*)d_in[7];
    const float* bo = (const float*)d_in[8];
    float* out = (float*)d_out;

    __nv_bfloat16 *xhi, *xlo, *whi, *wlo;
    __nv_bfloat16 *qthi, *qtlo, *kthi, *ktlo, *vhi, *vlo, *ahi, *alo;
    cudaGetSymbolAddress((void**)&xhi, g_xhi);
    cudaGetSymbolAddress((void**)&xlo, g_xlo);
    cudaGetSymbolAddress((void**)&whi, g_wt_hi);
    cudaGetSymbolAddress((void**)&wlo, g_wt_lo);
    cudaGetSymbolAddress((void**)&qthi, g_QThi);
    cudaGetSymbolAddress((void**)&qtlo, g_QTlo);
    cudaGetSymbolAddress((void**)&kthi, g_KThi);
    cudaGetSymbolAddress((void**)&ktlo, g_KTlo);
    cudaGetSymbolAddress((void**)&vhi, g_Vhi);
    cudaGetSymbolAddress((void**)&vlo, g_Vlo);
    cudaGetSymbolAddress((void**)&ahi, g_Ahi);
    cudaGetSymbolAddress((void**)&alo, g_Alo);

    cudaFuncSetAttribute(gemm_mma_kernel, cudaFuncAttributeMaxDynamicSharedMemorySize,
                         GSMEM_BYTES);
    cudaFuncSetAttribute(attn_mma_kernel, cudaFuncAttributeMaxDynamicSharedMemorySize,
                         ATT_SMEM);

    // 1) split x
    split_f32_kernel<<<2048, 256>>>(x, xhi, xlo, BLN * DIM / 4);

    // 2) transpose+split weights (W^T [n][k])
    dim3 tgrid(32, 32), tblk(32, 8);
    transpose_split_kernel<<<tgrid, tblk>>>(Wq, whi + 0 * DIM * DIM, wlo + 0 * DIM * DIM);
    transpose_split_kernel<<<tgrid, tblk>>>(Wk, whi + 1 * DIM * DIM, wlo + 1 * DIM * DIM);
    transpose_split_kernel<<<tgrid, tblk>>>(Wv, whi + 2 * DIM * DIM, wlo + 2 * DIM * DIM);
    transpose_split_kernel<<<tgrid, tblk>>>(Wo, whi + 3 * DIM * DIM, wlo + 3 * DIM * DIM);

    // 3) projections: Q,K -> transposed split; V -> natural split
    dim3 ggrid(8, 64);
    gemm_mma_kernel<<<ggrid, 256, GSMEM_BYTES>>>(xhi, xlo, whi + 0 * DIM * DIM,
                                                 wlo + 0 * DIM * DIM, bq,
                                                 nullptr, qthi, qtlo, QKSCALE, 2);
    gemm_mma_kernel<<<ggrid, 256, GSMEM_BYTES>>>(xhi, xlo, whi + 1 * DIM * DIM,
                                                 wlo + 1 * DIM * DIM, bk,
                                                 nullptr, kthi, ktlo, QKSCALE, 2);
    gemm_mma_kernel<<<ggrid, 256, GSMEM_BYTES>>>(xhi, xlo, whi + 2 * DIM * DIM,
                                                 wlo + 2 * DIM * DIM, bv,
                                                 nullptr, vhi, vlo, 1.0f, 1);

    // 4) attention (tensor-core, exact softmax), writes split A
    attn_mma_kernel<<<dim3(32, 128), 256, ATT_SMEM>>>();

    // 5) output projection (fp32 out)
    gemm_mma_kernel<<<ggrid, 256, GSMEM_BYTES>>>(ahi, alo, whi + 3 * DIM * DIM,
                                                 wlo + 3 * DIM * DIM, bo,
                                                 out, nullptr, nullptr, 1.0f, 0);
}

// round 6
// speedup vs baseline: 2.3526x; 1.2210x over previous
#include <cuda_runtime.h>
#include <cuda_bf16.h>
#include <cstdint>

// ===========================================================================
// Problem constants
// ===========================================================================
#define BLN 8192          // B*L
#define DIM 1024          // D
#define QKSCALE 0.03125f  // 1/sqrt(1024)

// ===========================================================================
// Device scratch (allocation-free rule: device globals)
// ===========================================================================
__device__ __nv_bfloat16 g_xhi[BLN * DIM];
__device__ __nv_bfloat16 g_xlo[BLN * DIM];
__device__ __nv_bfloat16 g_wt_hi[4][DIM * DIM];   // W^T [n][k] hi
__device__ __nv_bfloat16 g_wt_lo[4][DIM * DIM];   // W^T [n][k] lo
// Batch-transposed Q,K (hi only — 1-term path): [b][ch][l]
__device__ __nv_bfloat16 g_QThi[BLN * DIM];
__device__ __nv_bfloat16 g_KThi[BLN * DIM];
// Natural split V and attention output A: [row=(b,l)][ch]
__device__ __nv_bfloat16 g_Vhi[BLN * DIM];
__device__ __nv_bfloat16 g_Vlo[BLN * DIM];
__device__ __nv_bfloat16 g_Ahi[BLN * DIM];
__device__ __nv_bfloat16 g_Alo[BLN * DIM];

// ===========================================================================
// PTX helpers (sm_80-era: target is plain sm_100, tcgen05 unavailable)
// ===========================================================================
__device__ __forceinline__ uint32_t smem_u32(const void* p) {
    uint32_t a;
    asm("{ .reg .u64 t; cvta.to.shared.u64 t, %1; cvt.u32.u64 %0, t; }" : "=r"(a) : "l"(p));
    return a;
}
#define CP_ASYNC16(saddr, gptr) \
    asm volatile("cp.async.cg.shared.global [%0], [%1], 16;" :: "r"(saddr), "l"(gptr))
#define CP_COMMIT() asm volatile("cp.async.commit_group;" ::: "memory")
#define CP_WAIT(n)  asm volatile("cp.async.wait_group %0;" :: "n"(n) : "memory")

__device__ __forceinline__ void ldmx4(uint32_t& r0, uint32_t& r1, uint32_t& r2, uint32_t& r3,
                                      uint32_t addr) {
    asm volatile("ldmatrix.sync.aligned.m8n8.x4.shared.b16 {%0,%1,%2,%3}, [%4];"
                 : "=r"(r0), "=r"(r1), "=r"(r2), "=r"(r3) : "r"(addr));
}
__device__ __forceinline__ void ldmx2(uint32_t& r0, uint32_t& r1, uint32_t addr) {
    asm volatile("ldmatrix.sync.aligned.m8n8.x2.shared.b16 {%0,%1}, [%2];"
                 : "=r"(r0), "=r"(r1) : "r"(addr));
}
__device__ __forceinline__ void mma16816(float* c, const uint32_t* a, const uint32_t* b) {
    asm volatile(
        "mma.sync.aligned.m16n8k16.row.col.f32.bf16.bf16.f32 "
        "{%0,%1,%2,%3}, {%4,%5,%6,%7}, {%8,%9}, {%0,%1,%2,%3};"
        : "+f"(c[0]), "+f"(c[1]), "+f"(c[2]), "+f"(c[3])
        : "r"(a[0]), "r"(a[1]), "r"(a[2]), "r"(a[3]), "r"(b[0]), "r"(b[1]));
}

// ===========================================================================
// Split f32 -> (bf16 hi, bf16 lo)
// ===========================================================================
struct alignas(8) bf4 { __nv_bfloat16 a, b, c, d; };

__global__ void split_f32_kernel(const float* __restrict__ in,
                                 __nv_bfloat16* __restrict__ hi,
                                 __nv_bfloat16* __restrict__ lo, int n4) {
    int i = blockIdx.x * blockDim.x + threadIdx.x;
    int stride = gridDim.x * blockDim.x;
    for (; i < n4; i += stride) {
        float4 v = ((const float4*)in)[i];
        __nv_bfloat16 h0 = __float2bfloat16(v.x);
        __nv_bfloat16 h1 = __float2bfloat16(v.y);
        __nv_bfloat16 h2 = __float2bfloat16(v.z);
        __nv_bfloat16 h3 = __float2bfloat16(v.w);
        bf4 H = {h0, h1, h2, h3};
        bf4 L = {__float2bfloat16(v.x - __bfloat162float(h0)),
                 __float2bfloat16(v.y - __bfloat162float(h1)),
                 __float2bfloat16(v.z - __bfloat162float(h2)),
                 __float2bfloat16(v.w - __bfloat162float(h3))};
        ((bf4*)hi)[i] = H;
        ((bf4*)lo)[i] = L;
    }
}

// ===========================================================================
// Transpose + split: W [K][N] f32 -> W^T [N][K] bf16 hi/lo
// ===========================================================================
__global__ void transpose_split_kernel(const float* __restrict__ W,
                                       __nv_bfloat16* __restrict__ Thi,
                                       __nv_bfloat16* __restrict__ Tlo) {
    __shared__ float t[32][33];
    const int n0 = blockIdx.x << 5;
    const int k0 = blockIdx.y << 5;
    const int tx = threadIdx.x, ty = threadIdx.y;
#pragma unroll
    for (int j = 0; j < 4; j++)
        t[ty + (j << 3)][tx] = W[(k0 + ty + (j << 3)) * DIM + n0 + tx];
    __syncthreads();
#pragma unroll
    for (int j = 0; j < 4; j++) {
        float v = t[tx][ty + (j << 3)];
        __nv_bfloat16 h = __float2bfloat16(v);
        int o = (n0 + ty + (j << 3)) * DIM + k0 + tx;
        Thi[o] = h;
        Tlo[o] = __float2bfloat16(v - __bfloat162float(h));
    }
}

// ===========================================================================
// Tensor-core GEMM via mma.sync, TERMS-template split precision:
//   TERMS=3: Ahi*Bhi + Alo*Bhi + Ahi*Blo       TERMS=1: Ahi*Bhi only
// modes: 0 = fp32 natural (Cf)
//        1 = split-bf16 natural (Chi/Clo)
//        2 = bf16 batch-transposed [b][ch][l] (Chi; +Clo iff TERMS==3)
// ===========================================================================
#define GSTRIDE 40
#define GTILE_BYTES (128 * GSTRIDE * 2)
#define GSTAGE_BYTES (4 * GTILE_BYTES)
#define GSMEM_BYTES (2 * GSTAGE_BYTES)   // 81920 B

template <int TERMS>
__global__ __launch_bounds__(256, 1)
void gemm_mma_kernel(const __nv_bfloat16* __restrict__ Ahi,
                     const __nv_bfloat16* __restrict__ Alo,
                     const __nv_bfloat16* __restrict__ Bhi,
                     const __nv_bfloat16* __restrict__ Blo,
                     const float* __restrict__ bias,
                     float* __restrict__ Cf,
                     __nv_bfloat16* __restrict__ Chi,
                     __nv_bfloat16* __restrict__ Clo,
                     float scale, int mode) {
    extern __shared__ __align__(16) char smem[];
    const uint32_t sbase = smem_u32(smem);

    const int tid = threadIdx.x;
    const int wid = tid >> 5;
    const int lane = tid & 31;
    const int m0 = blockIdx.y << 7;
    const int n0 = blockIdx.x << 7;
    const int wm = (wid & 1) << 6;
    const int wn = (wid >> 1) << 5;

    const __nv_bfloat16* srcs[4] = {Ahi + m0 * 1024, Alo + m0 * 1024,
                                    Bhi + n0 * 1024, Blo + n0 * 1024};

    float acc[4][4][4];
#pragma unroll
    for (int a = 0; a < 4; a++)
#pragma unroll
        for (int b = 0; b < 4; b++)
#pragma unroll
            for (int c = 0; c < 4; c++) acc[a][b][c] = 0.f;

    const int a_r = lane & 15, a_k = lane >> 4;
    const int b_r = lane & 7, b_k = (lane >> 3) & 1;

    auto load_stage = [&](int kt, int buf) {
        const int kb = kt << 5;
        uint32_t sb = sbase + buf * GSTAGE_BYTES;
        constexpr int NLD = (TERMS == 3) ? 8 : 4;
#pragma unroll
        for (int i = 0; i < NLD; i++) {
            int tile, idx;
            if (TERMS == 3) {
                tile = i >> 1;
                idx = ((i & 1) << 8) + tid;
            } else {
                tile = (i >> 1) << 1;       // 0 (Ahi) or 2 (Bhi)
                idx = ((i & 1) << 8) + tid;
            }
            int row = idx >> 2;
            int ch = idx & 3;
            const __nv_bfloat16* g = srcs[tile] + row * 1024 + kb + (ch << 3);
            uint32_t s = sb + tile * GTILE_BYTES + (row * GSTRIDE + (ch << 3)) * 2;
            CP_ASYNC16(s, g);
        }
    };

    load_stage(0, 0);
    CP_COMMIT();

    for (int kt = 0; kt < 32; kt++) {
        const int buf = kt & 1;
        if (kt + 1 < 32) {
            load_stage(kt + 1, buf ^ 1);
            CP_COMMIT();
            CP_WAIT(1);
        } else {
            CP_WAIT(0);
        }
        __syncthreads();

        const uint32_t sb = sbase + buf * GSTAGE_BYTES;
        const uint32_t sAhi = sb;
        const uint32_t sAlo = sb + GTILE_BYTES;
        const uint32_t sBhi = sb + 2 * GTILE_BYTES;
        const uint32_t sBlo = sb + 3 * GTILE_BYTES;

#pragma unroll
        for (int ks = 0; ks < 2; ks++) {
            uint32_t ah[4][4], al[4][4], bh[4][2], bl[4][2];
#pragma unroll
            for (int mt = 0; mt < 4; mt++) {
                uint32_t off = ((wm + (mt << 4) + a_r) * GSTRIDE + (ks << 4) + (a_k << 3)) * 2;
                ldmx4(ah[mt][0], ah[mt][1], ah[mt][2], ah[mt][3], sAhi + off);
                if (TERMS == 3)
                    ldmx4(al[mt][0], al[mt][1], al[mt][2], al[mt][3], sAlo + off);
            }
#pragma unroll
            for (int nt = 0; nt < 4; nt++) {
                uint32_t off = ((wn + (nt << 3) + b_r) * GSTRIDE + (ks << 4) + (b_k << 3)) * 2;
                ldmx2(bh[nt][0], bh[nt][1], sBhi + off);
                if (TERMS == 3)
                    ldmx2(bl[nt][0], bl[nt][1], sBlo + off);
            }
#pragma unroll
            for (int mt = 0; mt < 4; mt++)
#pragma unroll
                for (int nt = 0; nt < 4; nt++) {
                    mma16816(acc[mt][nt], ah[mt], bh[nt]);
                    if (TERMS == 3) {
                        mma16816(acc[mt][nt], al[mt], bh[nt]);
                        mma16816(acc[mt][nt], ah[mt], bl[nt]);
                    }
                }
        }
        __syncthreads();
    }

    const int er = lane >> 2;
    const int ec = (lane & 3) << 1;

    if (mode == 0) {
#pragma unroll
        for (int mt = 0; mt < 4; mt++) {
#pragma unroll
            for (int nt = 0; nt < 4; nt++) {
                int row = m0 + wm + (mt << 4) + er;
                int col = n0 + wn + (nt << 3) + ec;
                float2 b2 = *(const float2*)(bias + col);
                float2 o0, o1;
                o0.x = (acc[mt][nt][0] + b2.x) * scale;
                o0.y = (acc[mt][nt][1] + b2.y) * scale;
                o1.x = (acc[mt][nt][2] + b2.x) * scale;
                o1.y = (acc[mt][nt][3] + b2.y) * scale;
                *(float2*)(Cf + row * 1024 + col) = o0;
                *(float2*)(Cf + (row + 8) * 1024 + col) = o1;
            }
        }
    } else if (mode == 1) {
#pragma unroll
        for (int mt = 0; mt < 4; mt++) {
#pragma unroll
            for (int nt = 0; nt < 4; nt++) {
                int row = m0 + wm + (mt << 4) + er;
                int col = n0 + wn + (nt << 3) + ec;
                float2 b2 = *(const float2*)(bias + col);
#pragma unroll
                for (int half = 0; half < 2; half++) {
                    int r = row + half * 8;
                    float v0 = (acc[mt][nt][half * 2 + 0] + b2.x) * scale;
                    float v1 = (acc[mt][nt][half * 2 + 1] + b2.y) * scale;
                    __nv_bfloat16 h0 = __float2bfloat16(v0);
                    __nv_bfloat16 h1 = __float2bfloat16(v1);
                    __nv_bfloat162 hp; hp.x = h0; hp.y = h1;
                    *(__nv_bfloat162*)(Chi + r * 1024 + col) = hp;
                    __nv_bfloat162 lp;
                    lp.x = __float2bfloat16(v0 - __bfloat162float(h0));
                    lp.y = __float2bfloat16(v1 - __bfloat162float(h1));
                    *(__nv_bfloat162*)(Clo + r * 1024 + col) = lp;
                }
            }
        }
    } else {
        // mode 2: transposed write via smem staging [n][m]; lo only if TERMS==3
        __nv_bfloat16* sthi = (__nv_bfloat16*)smem;
        __nv_bfloat16* stlo = (__nv_bfloat16*)(smem + 34816);
#pragma unroll
        for (int mt = 0; mt < 4; mt++) {
#pragma unroll
            for (int nt = 0; nt < 4; nt++) {
                int mrow = wm + (mt << 4) + er;
                int ncol = wn + (nt << 3) + ec;
                float2 b2 = *(const float2*)(bias + n0 + ncol);
#pragma unroll
                for (int half = 0; half < 2; half++) {
                    int r = mrow + half * 8;
                    float v0 = (acc[mt][nt][half * 2 + 0] + b2.x) * scale;
                    float v1 = (acc[mt][nt][half * 2 + 1] + b2.y) * scale;
                    __nv_bfloat16 h0 = __float2bfloat16(v0);
                    __nv_bfloat16 h1 = __float2bfloat16(v1);
                    sthi[ncol * 136 + r] = h0;
                    sthi[(ncol + 1) * 136 + r] = h1;
                    if (TERMS == 3) {
                        stlo[ncol * 136 + r] = __float2bfloat16(v0 - __bfloat162float(h0));
                        stlo[(ncol + 1) * 136 + r] = __float2bfloat16(v1 - __bfloat162float(h1));
                    }
                }
            }
        }
        __syncthreads();
        const int bidx = m0 >> 10;
        const int l0 = m0 & 1023;
        constexpr int NCP = (TERMS == 3) ? 16 : 8;
#pragma unroll
        for (int i = 0; i < NCP; i++) {
            int q = tid + (i << 8);
            int t = q >> 11;
            int idx = q & 2047;
            int nrow = idx >> 4;
            int ch = idx & 15;
            uint4 v = *(const uint4*)(smem + t * 34816 + (nrow * 136 + ch * 8) * 2);
            __nv_bfloat16* dst = (t ? Clo : Chi) +
                bidx * 1048576 + (n0 + nrow) * 1024 + l0 + ch * 8;
            *(uint4*)dst = v;
        }
    }
}

// ===========================================================================
// Attention with mma.sync, exact softmax.
// Phase1: S = Q^T K  — 1-term bf16 (S is ~N(0, 3e-3): absolute-error regime)
// Phase2: O = P V    — 3-term split (P,V both split bf16)
// ===========================================================================
#define AS_STRIDE 1032
#define ATT_R_OFF 132096
#define ATT_SMEM  219136

__global__ __launch_bounds__(256, 1)
void attn_mma_kernel() {
    extern __shared__ __align__(16) char sm[];
    float* S = (float*)sm;
    const uint32_t sb = smem_u32(sm);
    const uint32_t R = sb + ATT_R_OFF;

    const int g = blockIdx.y, qt = blockIdx.x;
    const int b = g >> 4, h = g & 15;
    const int tid = threadIdx.x, wid = tid >> 5, lane = tid & 31;

    const int qkbase = b * 1048576 + h * 64;

    const int a_r = lane & 15, a_k = lane >> 4;
    const int b_r = lane & 7, b_k = (lane >> 3) & 1;
    const int er = lane >> 2, ec = (lane & 3) << 1;

    // Phase-1 smem: Q hi [32x72] at R; K hi [128x72] x2 bufs at R+4608
    {
        int r = tid >> 3, ch = tid & 7;
        const __nv_bfloat16* src = g_QThi + qkbase + (qt * 32 + r) * 1024 + ch * 8;
        CP_ASYNC16(R + (r * 72 + ch * 8) * 2, src);
    }
    auto load_K = [&](int c, int buf) {
        int base = qkbase + c * 128 * 1024;
#pragma unroll
        for (int i = 0; i < 4; i++) {
            int q = tid + (i << 8);           // 0..1023
            int r = q >> 3, ch = q & 7;
            const __nv_bfloat16* src = g_KThi + base + r * 1024 + ch * 8;
            CP_ASYNC16(R + 4608 + buf * 18432 + (r * 72 + ch * 8) * 2, src);
        }
    };
    load_K(0, 0);
    CP_COMMIT();

    uint32_t qh[2][4][4];

    for (int c = 0; c < 8; c++) {
        const int buf = c & 1;
        __syncthreads();
        if (c + 1 < 8) {
            load_K(c + 1, buf ^ 1);
            CP_COMMIT();
            CP_WAIT(1);
        } else {
            CP_WAIT(0);
        }
        __syncthreads();
        if (c == 0) {
#pragma unroll
            for (int mt = 0; mt < 2; mt++)
#pragma unroll
                for (int ks = 0; ks < 4; ks++) {
                    uint32_t off = ((mt * 16 + a_r) * 72 + ks * 16 + a_k * 8) * 2;
                    ldmx4(qh[mt][ks][0], qh[mt][ks][1], qh[mt][ks][2], qh[mt][ks][3], R + off);
                }
        }
        float acc[2][2][4];
#pragma unroll
        for (int i = 0; i < 2; i++)
#pragma unroll
            for (int j = 0; j < 2; j++)
#pragma unroll
                for (int k = 0; k < 4; k++) acc[i][j][k] = 0.f;

        uint32_t kb = R + 4608 + buf * 18432;
#pragma unroll
        for (int ks = 0; ks < 4; ks++) {
            uint32_t bh[2][2];
#pragma unroll
            for (int nt = 0; nt < 2; nt++) {
                uint32_t off = ((wid * 16 + nt * 8 + b_r) * 72 + ks * 16 + b_k * 8) * 2;
                ldmx2(bh[nt][0], bh[nt][1], kb + off);
            }
#pragma unroll
            for (int mt = 0; mt < 2; mt++)
#pragma unroll
                for (int nt = 0; nt < 2; nt++)
                    mma16816(acc[mt][nt], qh[mt][ks], bh[nt]);
        }
#pragma unroll
        for (int mt = 0; mt < 2; mt++)
#pragma unroll
            for (int nt = 0; nt < 2; nt++) {
                int row = mt * 16 + er;
                int col = c * 128 + wid * 16 + nt * 8 + ec;
                *(float2*)&S[row * AS_STRIDE + col] =
                    make_float2(acc[mt][nt][0], acc[mt][nt][1]);
                *(float2*)&S[(row + 8) * AS_STRIDE + col] =
                    make_float2(acc[mt][nt][2], acc[mt][nt][3]);
            }
    }
    __syncthreads();

    // Phase-2: prefetch V0, softmax, then PV with 3-term split
    auto load_V = [&](int c, int buf) {
#pragma unroll
        for (int i = 0; i < 8; i++) {
            int q = tid + (i << 8);
            int t = q >> 10, idx = q & 1023;
            int r = idx >> 4, ch = idx & 15;
            const __nv_bfloat16* src =
                (t ? g_Vlo : g_Vhi) + (b * 1024 + h * 64 + r) * 1024 + c * 128 + ch * 8;
            uint32_t dst = R + 17408 + buf * 34816 + t * 17408 + (r * 136 + ch * 8) * 2;
            CP_ASYNC16(dst, src);
        }
    };
    load_V(0, 0);
    CP_COMMIT();

    {
#pragma unroll
        for (int rr = 0; rr < 4; rr++) {
            float* row = S + (wid * 4 + rr) * AS_STRIDE;
            float m = -1e30f;
            for (int cc = lane; cc < 1024; cc += 32) m = fmaxf(m, row[cc]);
#pragma unroll
            for (int o = 16; o > 0; o >>= 1) m = fmaxf(m, __shfl_xor_sync(0xffffffffu, m, o));
            float s = 0.f;
            for (int cc = lane; cc < 1024; cc += 32) {
                float e = __expf(row[cc] - m);
                row[cc] = e;
                s += e;
            }
#pragma unroll
            for (int o = 16; o > 0; o >>= 1) s += __shfl_xor_sync(0xffffffffu, s, o);
            float inv = 1.0f / s;
            for (int cc = lane; cc < 1024; cc += 32) row[cc] *= inv;
        }
    }
    __syncthreads();

    __nv_bfloat16* Ph = (__nv_bfloat16*)(sm + ATT_R_OFF);
    __nv_bfloat16* Pl = (__nv_bfloat16*)(sm + ATT_R_OFF + 8704);

    float oacc[2][4];
#pragma unroll
    for (int i = 0; i < 2; i++)
#pragma unroll
        for (int j = 0; j < 4; j++) oacc[i][j] = 0.f;

    for (int c = 0; c < 8; c++) {
        const int buf = c & 1;
        __syncthreads();
        if (c + 1 < 8) {
            load_V(c + 1, buf ^ 1);
            CP_COMMIT();
        }
        {
            int r = tid >> 3, c0 = (tid & 7) * 16;
            const float* srow = S + r * AS_STRIDE + c * 128 + c0;
            __nv_bfloat16* phr = Ph + r * 136 + c0;
            __nv_bfloat16* plr = Pl + r * 136 + c0;
#pragma unroll
            for (int j = 0; j < 16; j++) {
                float v = srow[j];
                __nv_bfloat16 hh = __float2bfloat16(v);
                phr[j] = hh;
                plr[j] = __float2bfloat16(v - __bfloat162float(hh));
            }
        }
        if (c + 1 < 8) CP_WAIT(1); else CP_WAIT(0);
        __syncthreads();

        uint32_t vb = R + 17408 + buf * 34816;
#pragma unroll
        for (int ks = 0; ks < 8; ks++) {
            uint32_t ph[2][4], pl[2][4], vh[2], vl[2];
#pragma unroll
            for (int mt = 0; mt < 2; mt++) {
                uint32_t off = R + ((mt * 16 + a_r) * 136 + ks * 16 + a_k * 8) * 2;
                ldmx4(ph[mt][0], ph[mt][1], ph[mt][2], ph[mt][3], off);
                ldmx4(pl[mt][0], pl[mt][1], pl[mt][2], pl[mt][3], off + 8704);
            }
            uint32_t voff = vb + ((wid * 8 + b_r) * 136 + ks * 16 + b_k * 8) * 2;
            ldmx2(vh[0], vh[1], voff);
            ldmx2(vl[0], vl[1], voff + 17408);
#pragma unroll
            for (int mt = 0; mt < 2; mt++) {
                mma16816(oacc[mt], ph[mt], vh);
                mma16816(oacc[mt], pl[mt], vh);
                mma16816(oacc[mt], ph[mt], vl);
            }
        }
    }

    // write O as split bf16 (reference scatter)
#pragma unroll
    for (int mt = 0; mt < 2; mt++) {
#pragma unroll
        for (int half = 0; half < 2; half++) {
            int t1 = qt * 32 + mt * 16 + er + half * 8;
            int p = t1 >> 4, qq = t1 & 15;
            int col = wid * 8 + ec;
            int off = (b * 1024 + h * 64 + p) * 1024 + qq * 64 + col;
            float v0 = oacc[mt][half * 2 + 0];
            float v1 = oacc[mt][half * 2 + 1];
            __nv_bfloat16 h0 = __float2bfloat16(v0);
            __nv_bfloat16 h1 = __float2bfloat16(v1);
            __nv_bfloat162 hp; hp.x = h0; hp.y = h1;
            *(__nv_bfloat162*)(g_Ahi + off) = hp;
            __nv_bfloat162 lp;
            lp.x = __float2bfloat16(v0 - __bfloat162float(h0));
            lp.y = __float2bfloat16(v1 - __bfloat162float(h1));
            *(__nv_bfloat162*)(g_Alo + off) = lp;
        }
    }
}

// ===========================================================================
extern "C" void kernel_launch(void* const* d_in, const int* in_sizes, int n_in,
                              void* d_out, int out_size) {
    const float* x  = (const float*)d_in[0];
    const float* Wq = (const float*)d_in[1];
    const float* bq = (const float*)d_in[2];
    const float* Wk = (const float*)d_in[3];
    const float* bk = (const float*)d_in[4];
    const float* Wv = (const float*)d_in[5];
    const float* bv = (const float*)d_in[6];
    const float* Wo = (const float*)d_in[7];
    const float* bo = (const float*)d_in[8];
    float* out = (float*)d_out;

    __nv_bfloat16 *xhi, *xlo, *whi, *wlo;
    __nv_bfloat16 *qthi, *kthi, *vhi, *vlo, *ahi, *alo;
    cudaGetSymbolAddress((void**)&xhi, g_xhi);
    cudaGetSymbolAddress((void**)&xlo, g_xlo);
    cudaGetSymbolAddress((void**)&whi, g_wt_hi);
    cudaGetSymbolAddress((void**)&wlo, g_wt_lo);
    cudaGetSymbolAddress((void**)&qthi, g_QThi);
    cudaGetSymbolAddress((void**)&kthi, g_KThi);
    cudaGetSymbolAddress((void**)&vhi, g_Vhi);
    cudaGetSymbolAddress((void**)&vlo, g_Vlo);
    cudaGetSymbolAddress((void**)&ahi, g_Ahi);
    cudaGetSymbolAddress((void**)&alo, g_Alo);

    cudaFuncSetAttribute(gemm_mma_kernel<1>, cudaFuncAttributeMaxDynamicSharedMemorySize,
                         GSMEM_BYTES);
    cudaFuncSetAttribute(gemm_mma_kernel<3>, cudaFuncAttributeMaxDynamicSharedMemorySize,
                         GSMEM_BYTES);
    cudaFuncSetAttribute(attn_mma_kernel, cudaFuncAttributeMaxDynamicSharedMemorySize,
                         ATT_SMEM);

    // 1) split x
    split_f32_kernel<<<2048, 256>>>(x, xhi, xlo, BLN * DIM / 4);

    // 2) transpose+split weights (W^T [n][k])
    dim3 tgrid(32, 32), tblk(32, 8);
    transpose_split_kernel<<<tgrid, tblk>>>(Wq, whi + 0 * DIM * DIM, wlo + 0 * DIM * DIM);
    transpose_split_kernel<<<tgrid, tblk>>>(Wk, whi + 1 * DIM * DIM, wlo + 1 * DIM * DIM);
    transpose_split_kernel<<<tgrid, tblk>>>(Wv, whi + 2 * DIM * DIM, wlo + 2 * DIM * DIM);
    transpose_split_kernel<<<tgrid, tblk>>>(Wo, whi + 3 * DIM * DIM, wlo + 3 * DIM * DIM);

    // 3) projections: Q,K 1-term transposed-hi; V 3-term natural split
    dim3 ggrid(8, 64);
    gemm_mma_kernel<1><<<ggrid, 256, GSMEM_BYTES>>>(xhi, xlo, whi + 0 * DIM * DIM,
                                                    wlo + 0 * DIM * DIM, bq,
                                                    nullptr, qthi, nullptr, QKSCALE, 2);
    gemm_mma_kernel<1><<<ggrid, 256, GSMEM_BYTES>>>(xhi, xlo, whi + 1 * DIM * DIM,
                                                    wlo + 1 * DIM * DIM, bk,
                                                    nullptr, kthi, nullptr, QKSCALE, 2);
    gemm_mma_kernel<3><<<ggrid, 256, GSMEM_BYTES>>>(xhi, xlo, whi + 2 * DIM * DIM,
                                                    wlo + 2 * DIM * DIM, bv,
                                                    nullptr, vhi, vlo, 1.0f, 1);

    // 4) attention
    attn_mma_kernel<<<dim3(32, 128), 256, ATT_SMEM>>>();

    // 5) output projection (3-term, fp32 out)
    gemm_mma_kernel<3><<<ggrid, 256, GSMEM_BYTES>>>(ahi, alo, whi + 3 * DIM * DIM,
                                                    wlo + 3 * DIM * DIM, bo,
                                                    out, nullptr, nullptr, 1.0f, 0);
}

// round 7
// speedup vs baseline: 2.5660x; 1.0907x over previous
#include <cuda_runtime.h>
#include <cuda_bf16.h>
#include <cstdint>

// ===========================================================================
// Problem constants
// ===========================================================================
#define BLN 8192          // B*L
#define DIM 1024          // D
#define QKSCALE 0.03125f  // 1/sqrt(1024)

// ===========================================================================
// Device scratch (allocation-free rule: device globals)
// ===========================================================================
__device__ __nv_bfloat16 g_xhi[BLN * DIM];
__device__ __nv_bfloat16 g_xlo[BLN * DIM];
__device__ __nv_bfloat16 g_wt_hi[4][DIM * DIM];   // W^T [n][k] hi
__device__ __nv_bfloat16 g_wt_lo[4][DIM * DIM];   // W^T [n][k] lo
// Batch-transposed Q,K (hi only — 1-term path): [b][ch][l]
__device__ __nv_bfloat16 g_QThi[BLN * DIM];
__device__ __nv_bfloat16 g_KThi[BLN * DIM];
// Natural split V and attention output A: [row=(b,l)][ch]
__device__ __nv_bfloat16 g_Vhi[BLN * DIM];
__device__ __nv_bfloat16 g_Vlo[BLN * DIM];
__device__ __nv_bfloat16 g_Ahi[BLN * DIM];
__device__ __nv_bfloat16 g_Alo[BLN * DIM];

// ===========================================================================
// PTX helpers (sm_80-era: target is plain sm_100, tcgen05 unavailable)
// ===========================================================================
__device__ __forceinline__ uint32_t smem_u32(const void* p) {
    uint32_t a;
    asm("{ .reg .u64 t; cvta.to.shared.u64 t, %1; cvt.u32.u64 %0, t; }" : "=r"(a) : "l"(p));
    return a;
}
#define CP_ASYNC16(saddr, gptr) \
    asm volatile("cp.async.cg.shared.global [%0], [%1], 16;" :: "r"(saddr), "l"(gptr))
#define CP_COMMIT() asm volatile("cp.async.commit_group;" ::: "memory")
#define CP_WAIT(n)  asm volatile("cp.async.wait_group %0;" :: "n"(n) : "memory")

__device__ __forceinline__ void ldmx4(uint32_t& r0, uint32_t& r1, uint32_t& r2, uint32_t& r3,
                                      uint32_t addr) {
    asm volatile("ldmatrix.sync.aligned.m8n8.x4.shared.b16 {%0,%1,%2,%3}, [%4];"
                 : "=r"(r0), "=r"(r1), "=r"(r2), "=r"(r3) : "r"(addr));
}
__device__ __forceinline__ void ldmx2(uint32_t& r0, uint32_t& r1, uint32_t addr) {
    asm volatile("ldmatrix.sync.aligned.m8n8.x2.shared.b16 {%0,%1}, [%2];"
                 : "=r"(r0), "=r"(r1) : "r"(addr));
}
__device__ __forceinline__ void mma16816(float* c, const uint32_t* a, const uint32_t* b) {
    asm volatile(
        "mma.sync.aligned.m16n8k16.row.col.f32.bf16.bf16.f32 "
        "{%0,%1,%2,%3}, {%4,%5,%6,%7}, {%8,%9}, {%0,%1,%2,%3};"
        : "+f"(c[0]), "+f"(c[1]), "+f"(c[2]), "+f"(c[3])
        : "r"(a[0]), "r"(a[1]), "r"(a[2]), "r"(a[3]), "r"(b[0]), "r"(b[1]));
}

// ===========================================================================
// Split f32 -> (bf16 hi, bf16 lo)
// ===========================================================================
struct alignas(8) bf4 { __nv_bfloat16 a, b, c, d; };

__global__ void split_f32_kernel(const float* __restrict__ in,
                                 __nv_bfloat16* __restrict__ hi,
                                 __nv_bfloat16* __restrict__ lo, int n4) {
    int i = blockIdx.x * blockDim.x + threadIdx.x;
    int stride = gridDim.x * blockDim.x;
    for (; i < n4; i += stride) {
        float4 v = ((const float4*)in)[i];
        __nv_bfloat16 h0 = __float2bfloat16(v.x);
        __nv_bfloat16 h1 = __float2bfloat16(v.y);
        __nv_bfloat16 h2 = __float2bfloat16(v.z);
        __nv_bfloat16 h3 = __float2bfloat16(v.w);
        bf4 H = {h0, h1, h2, h3};
        bf4 L = {__float2bfloat16(v.x - __bfloat162float(h0)),
                 __float2bfloat16(v.y - __bfloat162float(h1)),
                 __float2bfloat16(v.z - __bfloat162float(h2)),
                 __float2bfloat16(v.w - __bfloat162float(h3))};
        ((bf4*)hi)[i] = H;
        ((bf4*)lo)[i] = L;
    }
}

// ===========================================================================
// Transpose + split: W [K][N] f32 -> W^T [N][K] bf16 hi/lo
// ===========================================================================
__global__ void transpose_split_kernel(const float* __restrict__ W,
                                       __nv_bfloat16* __restrict__ Thi,
                                       __nv_bfloat16* __restrict__ Tlo) {
    __shared__ float t[32][33];
    const int n0 = blockIdx.x << 5;
    const int k0 = blockIdx.y << 5;
    const int tx = threadIdx.x, ty = threadIdx.y;
#pragma unroll
    for (int j = 0; j < 4; j++)
        t[ty + (j << 3)][tx] = W[(k0 + ty + (j << 3)) * DIM + n0 + tx];
    __syncthreads();
#pragma unroll
    for (int j = 0; j < 4; j++) {
        float v = t[tx][ty + (j << 3)];
        __nv_bfloat16 h = __float2bfloat16(v);
        int o = (n0 + ty + (j << 3)) * DIM + k0 + tx;
        Thi[o] = h;
        Tlo[o] = __float2bfloat16(v - __bfloat162float(h));
    }
}

// ===========================================================================
// Tensor-core GEMM via mma.sync, TERMS split terms, 3-stage cp.async pipeline.
// modes: 0 = fp32 natural; 1 = split-bf16 natural; 2 = bf16 transposed [b][ch][l]
// ===========================================================================
#define GSTRIDE 40
#define GTILE_BYTES (128 * GSTRIDE * 2)
#define GSTAGE_BYTES (4 * GTILE_BYTES)
#define GSMEM_BYTES (3 * GSTAGE_BYTES)   // 122880 B (3 stages)

template <int TERMS>
__global__ __launch_bounds__(256, 1)
void gemm_mma_kernel(const __nv_bfloat16* __restrict__ Ahi,
                     const __nv_bfloat16* __restrict__ Alo,
                     const __nv_bfloat16* __restrict__ Bhi,
                     const __nv_bfloat16* __restrict__ Blo,
                     const float* __restrict__ bias,
                     float* __restrict__ Cf,
                     __nv_bfloat16* __restrict__ Chi,
                     __nv_bfloat16* __restrict__ Clo,
                     float scale, int mode) {
    extern __shared__ __align__(16) char smem[];
    const uint32_t sbase = smem_u32(smem);

    const int tid = threadIdx.x;
    const int wid = tid >> 5;
    const int lane = tid & 31;
    const int m0 = blockIdx.y << 7;
    const int n0 = blockIdx.x << 7;
    const int wm = (wid & 1) << 6;
    const int wn = (wid >> 1) << 5;

    const __nv_bfloat16* srcs[4] = {Ahi + m0 * 1024, Alo + m0 * 1024,
                                    Bhi + n0 * 1024, Blo + n0 * 1024};

    float acc[4][4][4];
#pragma unroll
    for (int a = 0; a < 4; a++)
#pragma unroll
        for (int b = 0; b < 4; b++)
#pragma unroll
            for (int c = 0; c < 4; c++) acc[a][b][c] = 0.f;

    const int a_r = lane & 15, a_k = lane >> 4;
    const int b_r = lane & 7, b_k = (lane >> 3) & 1;

    auto load_stage = [&](int kt, int buf) {
        const int kb = kt << 5;
        uint32_t sb = sbase + buf * GSTAGE_BYTES;
        constexpr int NLD = (TERMS == 3) ? 8 : 4;
#pragma unroll
        for (int i = 0; i < NLD; i++) {
            int tile, idx;
            if (TERMS == 3) {
                tile = i >> 1;
                idx = ((i & 1) << 8) + tid;
            } else {
                tile = (i >> 1) << 1;       // 0 (Ahi) or 2 (Bhi)
                idx = ((i & 1) << 8) + tid;
            }
            int row = idx >> 2;
            int ch = idx & 3;
            const __nv_bfloat16* g = srcs[tile] + row * 1024 + kb + (ch << 3);
            uint32_t s = sb + tile * GTILE_BYTES + (row * GSTRIDE + (ch << 3)) * 2;
            CP_ASYNC16(s, g);
        }
    };

    load_stage(0, 0); CP_COMMIT();
    load_stage(1, 1); CP_COMMIT();

    for (int kt = 0; kt < 32; kt++) {
        if (kt == 31) { CP_WAIT(0); } else { CP_WAIT(1); }
        __syncthreads();   // all warps done with stage kt-1 -> buffer (kt+2)%3 free
        if (kt + 2 < 32) { load_stage(kt + 2, (kt + 2) % 3); CP_COMMIT(); }

        const uint32_t sb = sbase + (kt % 3) * GSTAGE_BYTES;
        const uint32_t sAhi = sb;
        const uint32_t sAlo = sb + GTILE_BYTES;
        const uint32_t sBhi = sb + 2 * GTILE_BYTES;
        const uint32_t sBlo = sb + 3 * GTILE_BYTES;

#pragma unroll
        for (int ks = 0; ks < 2; ks++) {
            uint32_t ah[4][4], al[4][4], bh[4][2], bl[4][2];
#pragma unroll
            for (int mt = 0; mt < 4; mt++) {
                uint32_t off = ((wm + (mt << 4) + a_r) * GSTRIDE + (ks << 4) + (a_k << 3)) * 2;
                ldmx4(ah[mt][0], ah[mt][1], ah[mt][2], ah[mt][3], sAhi + off);
                if (TERMS == 3)
                    ldmx4(al[mt][0], al[mt][1], al[mt][2], al[mt][3], sAlo + off);
            }
#pragma unroll
            for (int nt = 0; nt < 4; nt++) {
                uint32_t off = ((wn + (nt << 3) + b_r) * GSTRIDE + (ks << 4) + (b_k << 3)) * 2;
                ldmx2(bh[nt][0], bh[nt][1], sBhi + off);
                if (TERMS == 3)
                    ldmx2(bl[nt][0], bl[nt][1], sBlo + off);
            }
#pragma unroll
            for (int mt = 0; mt < 4; mt++)
#pragma unroll
                for (int nt = 0; nt < 4; nt++) {
                    mma16816(acc[mt][nt], ah[mt], bh[nt]);
                    if (TERMS == 3) {
                        mma16816(acc[mt][nt], al[mt], bh[nt]);
                        mma16816(acc[mt][nt], ah[mt], bl[nt]);
                    }
                }
        }
    }
    __syncthreads();   // smem reuse safety for mode-2 staging

    const int er = lane >> 2;
    const int ec = (lane & 3) << 1;

    if (mode == 0) {
#pragma unroll
        for (int mt = 0; mt < 4; mt++) {
#pragma unroll
            for (int nt = 0; nt < 4; nt++) {
                int row = m0 + wm + (mt << 4) + er;
                int col = n0 + wn + (nt << 3) + ec;
                float2 b2 = *(const float2*)(bias + col);
                float2 o0, o1;
                o0.x = (acc[mt][nt][0] + b2.x) * scale;
                o0.y = (acc[mt][nt][1] + b2.y) * scale;
                o1.x = (acc[mt][nt][2] + b2.x) * scale;
                o1.y = (acc[mt][nt][3] + b2.y) * scale;
                *(float2*)(Cf + row * 1024 + col) = o0;
                *(float2*)(Cf + (row + 8) * 1024 + col) = o1;
            }
        }
    } else if (mode == 1) {
#pragma unroll
        for (int mt = 0; mt < 4; mt++) {
#pragma unroll
            for (int nt = 0; nt < 4; nt++) {
                int row = m0 + wm + (mt << 4) + er;
                int col = n0 + wn + (nt << 3) + ec;
                float2 b2 = *(const float2*)(bias + col);
#pragma unroll
                for (int half = 0; half < 2; half++) {
                    int r = row + half * 8;
                    float v0 = (acc[mt][nt][half * 2 + 0] + b2.x) * scale;
                    float v1 = (acc[mt][nt][half * 2 + 1] + b2.y) * scale;
                    __nv_bfloat16 h0 = __float2bfloat16(v0);
                    __nv_bfloat16 h1 = __float2bfloat16(v1);
                    __nv_bfloat162 hp; hp.x = h0; hp.y = h1;
                    *(__nv_bfloat162*)(Chi + r * 1024 + col) = hp;
                    __nv_bfloat162 lp;
                    lp.x = __float2bfloat16(v0 - __bfloat162float(h0));
                    lp.y = __float2bfloat16(v1 - __bfloat162float(h1));
                    *(__nv_bfloat162*)(Clo + r * 1024 + col) = lp;
                }
            }
        }
    } else {
        // mode 2: transposed write via smem staging [n][m]; lo only if TERMS==3
        __nv_bfloat16* sthi = (__nv_bfloat16*)smem;
        __nv_bfloat16* stlo = (__nv_bfloat16*)(smem + 34816);
#pragma unroll
        for (int mt = 0; mt < 4; mt++) {
#pragma unroll
            for (int nt = 0; nt < 4; nt++) {
                int mrow = wm + (mt << 4) + er;
                int ncol = wn + (nt << 3) + ec;
                float2 b2 = *(const float2*)(bias + n0 + ncol);
#pragma unroll
                for (int half = 0; half < 2; half++) {
                    int r = mrow + half * 8;
                    float v0 = (acc[mt][nt][half * 2 + 0] + b2.x) * scale;
                    float v1 = (acc[mt][nt][half * 2 + 1] + b2.y) * scale;
                    __nv_bfloat16 h0 = __float2bfloat16(v0);
                    __nv_bfloat16 h1 = __float2bfloat16(v1);
                    sthi[ncol * 136 + r] = h0;
                    sthi[(ncol + 1) * 136 + r] = h1;
                    if (TERMS == 3) {
                        stlo[ncol * 136 + r] = __float2bfloat16(v0 - __bfloat162float(h0));
                        stlo[(ncol + 1) * 136 + r] = __float2bfloat16(v1 - __bfloat162float(h1));
                    }
                }
            }
        }
        __syncthreads();
        const int bidx = m0 >> 10;
        const int l0 = m0 & 1023;
        constexpr int NCP = (TERMS == 3) ? 16 : 8;
#pragma unroll
        for (int i = 0; i < NCP; i++) {
            int q = tid + (i << 8);
            int t = q >> 11;
            int idx = q & 2047;
            int nrow = idx >> 4;
            int ch = idx & 15;
            uint4 v = *(const uint4*)(smem + t * 34816 + (nrow * 136 + ch * 8) * 2);
            __nv_bfloat16* dst = (t ? Clo : Chi) +
                bidx * 1048576 + (n0 + nrow) * 1024 + l0 + ch * 8;
            *(uint4*)dst = v;
        }
    }
}

// ===========================================================================
// Attention with mma.sync, exact softmax.
// Phase1: S = Q^T K  — 1-term bf16
// Phase2: O = P V    — 3-term split; K-SPLIT across warps: warp w owns t2-slice
//   w*16 of each 128-chunk and computes a full 32x64 partial; 8-way smem reduce.
// ===========================================================================
#define AS_STRIDE 1032
#define ATT_R_OFF 132096
#define ATT_SMEM  219136

__global__ __launch_bounds__(256, 1)
void attn_mma_kernel() {
    extern __shared__ __align__(16) char sm[];
    float* S = (float*)sm;
    const uint32_t sb = smem_u32(sm);
    const uint32_t R = sb + ATT_R_OFF;

    const int g = blockIdx.y, qt = blockIdx.x;
    const int b = g >> 4, h = g & 15;
    const int tid = threadIdx.x, wid = tid >> 5, lane = tid & 31;

    const int qkbase = b * 1048576 + h * 64;

    const int a_r = lane & 15, a_k = lane >> 4;
    const int b_r = lane & 7, b_k = (lane >> 3) & 1;
    const int er = lane >> 2, ec = (lane & 3) << 1;

    // Phase-1 smem: Q hi [32x72] at R; K hi [128x72] x2 bufs at R+4608
    {
        int r = tid >> 3, ch = tid & 7;
        const __nv_bfloat16* src = g_QThi + qkbase + (qt * 32 + r) * 1024 + ch * 8;
        CP_ASYNC16(R + (r * 72 + ch * 8) * 2, src);
    }
    auto load_K = [&](int c, int buf) {
        int base = qkbase + c * 128 * 1024;
#pragma unroll
        for (int i = 0; i < 4; i++) {
            int q = tid + (i << 8);
            int r = q >> 3, ch = q & 7;
            const __nv_bfloat16* src = g_KThi + base + r * 1024 + ch * 8;
            CP_ASYNC16(R + 4608 + buf * 18432 + (r * 72 + ch * 8) * 2, src);
        }
    };
    load_K(0, 0);
    CP_COMMIT();

    uint32_t qh[2][4][4];

    for (int c = 0; c < 8; c++) {
        const int buf = c & 1;
        __syncthreads();
        if (c + 1 < 8) {
            load_K(c + 1, buf ^ 1);
            CP_COMMIT();
            CP_WAIT(1);
        } else {
            CP_WAIT(0);
        }
        __syncthreads();
        if (c == 0) {
#pragma unroll
            for (int mt = 0; mt < 2; mt++)
#pragma unroll
                for (int ks = 0; ks < 4; ks++) {
                    uint32_t off = ((mt * 16 + a_r) * 72 + ks * 16 + a_k * 8) * 2;
                    ldmx4(qh[mt][ks][0], qh[mt][ks][1], qh[mt][ks][2], qh[mt][ks][3], R + off);
                }
        }
        float acc[2][2][4];
#pragma unroll
        for (int i = 0; i < 2; i++)
#pragma unroll
            for (int j = 0; j < 2; j++)
#pragma unroll
                for (int k = 0; k < 4; k++) acc[i][j][k] = 0.f;

        uint32_t kb = R + 4608 + buf * 18432;
#pragma unroll
        for (int ks = 0; ks < 4; ks++) {
            uint32_t bh[2][2];
#pragma unroll
            for (int nt = 0; nt < 2; nt++) {
                uint32_t off = ((wid * 16 + nt * 8 + b_r) * 72 + ks * 16 + b_k * 8) * 2;
                ldmx2(bh[nt][0], bh[nt][1], kb + off);
            }
#pragma unroll
            for (int mt = 0; mt < 2; mt++)
#pragma unroll
                for (int nt = 0; nt < 2; nt++)
                    mma16816(acc[mt][nt], qh[mt][ks], bh[nt]);
        }
#pragma unroll
        for (int mt = 0; mt < 2; mt++)
#pragma unroll
            for (int nt = 0; nt < 2; nt++) {
                int row = mt * 16 + er;
                int col = c * 128 + wid * 16 + nt * 8 + ec;
                *(float2*)&S[row * AS_STRIDE + col] =
                    make_float2(acc[mt][nt][0], acc[mt][nt][1]);
                *(float2*)&S[(row + 8) * AS_STRIDE + col] =
                    make_float2(acc[mt][nt][2], acc[mt][nt][3]);
            }
    }
    __syncthreads();

    // Phase-2: prefetch V0, softmax, then K-split PV
    auto load_V = [&](int c, int buf) {
#pragma unroll
        for (int i = 0; i < 8; i++) {
            int q = tid + (i << 8);
            int t = q >> 10, idx = q & 1023;
            int r = idx >> 4, ch = idx & 15;
            const __nv_bfloat16* src =
                (t ? g_Vlo : g_Vhi) + (b * 1024 + h * 64 + r) * 1024 + c * 128 + ch * 8;
            uint32_t dst = R + 17408 + buf * 34816 + t * 17408 + (r * 136 + ch * 8) * 2;
            CP_ASYNC16(dst, src);
        }
    };
    load_V(0, 0);
    CP_COMMIT();

    {
#pragma unroll
        for (int rr = 0; rr < 4; rr++) {
            float* row = S + (wid * 4 + rr) * AS_STRIDE;
            float m = -1e30f;
            for (int cc = lane; cc < 1024; cc += 32) m = fmaxf(m, row[cc]);
#pragma unroll
            for (int o = 16; o > 0; o >>= 1) m = fmaxf(m, __shfl_xor_sync(0xffffffffu, m, o));
            float s = 0.f;
            for (int cc = lane; cc < 1024; cc += 32) {
                float e = __expf(row[cc] - m);
                row[cc] = e;
                s += e;
            }
#pragma unroll
            for (int o = 16; o > 0; o >>= 1) s += __shfl_xor_sync(0xffffffffu, s, o);
            float inv = 1.0f / s;
            for (int cc = lane; cc < 1024; cc += 32) row[cc] *= inv;
        }
    }
    __syncthreads();

    __nv_bfloat16* Ph = (__nv_bfloat16*)(sm + ATT_R_OFF);
    __nv_bfloat16* Pl = (__nv_bfloat16*)(sm + ATT_R_OFF + 8704);

    float oacc[2][8][4];
#pragma unroll
    for (int i = 0; i < 2; i++)
#pragma unroll
        for (int j = 0; j < 8; j++)
#pragma unroll
            for (int k = 0; k < 4; k++) oacc[i][j][k] = 0.f;

    const int ksoff = wid * 16;   // this warp's t2-slice within each chunk

    for (int c = 0; c < 8; c++) {
        const int buf = c & 1;
        __syncthreads();
        if (c + 1 < 8) {
            load_V(c + 1, buf ^ 1);
            CP_COMMIT();
        }
        // convert P chunk fp32 -> split bf16 (vectorized bf16x2 stores)
        {
            int r = tid >> 3, c0 = (tid & 7) * 16;
            const float* srow = S + r * AS_STRIDE + c * 128 + c0;
            __nv_bfloat162* phr = (__nv_bfloat162*)(Ph + r * 136 + c0);
            __nv_bfloat162* plr = (__nv_bfloat162*)(Pl + r * 136 + c0);
#pragma unroll
            for (int j = 0; j < 8; j++) {
                float v0 = srow[2 * j], v1 = srow[2 * j + 1];
                __nv_bfloat16 h0 = __float2bfloat16(v0);
                __nv_bfloat16 h1 = __float2bfloat16(v1);
                __nv_bfloat162 hp; hp.x = h0; hp.y = h1;
                phr[j] = hp;
                __nv_bfloat162 lp;
                lp.x = __float2bfloat16(v0 - __bfloat162float(h0));
                lp.y = __float2bfloat16(v1 - __bfloat162float(h1));
                plr[j] = lp;
            }
        }
        if (c + 1 < 8) CP_WAIT(1); else CP_WAIT(0);
        __syncthreads();

        uint32_t vb = R + 17408 + buf * 34816;
        uint32_t ph[2][4], pl[2][4], vh[8][2], vl[8][2];
#pragma unroll
        for (int mt = 0; mt < 2; mt++) {
            uint32_t off = R + ((mt * 16 + a_r) * 136 + ksoff + a_k * 8) * 2;
            ldmx4(ph[mt][0], ph[mt][1], ph[mt][2], ph[mt][3], off);
            ldmx4(pl[mt][0], pl[mt][1], pl[mt][2], pl[mt][3], off + 8704);
        }
#pragma unroll
        for (int nt = 0; nt < 8; nt++) {
            uint32_t voff = vb + ((nt * 8 + b_r) * 136 + ksoff + b_k * 8) * 2;
            ldmx2(vh[nt][0], vh[nt][1], voff);
            ldmx2(vl[nt][0], vl[nt][1], voff + 17408);
        }
#pragma unroll
        for (int mt = 0; mt < 2; mt++)
#pragma unroll
            for (int nt = 0; nt < 8; nt++) {
                mma16816(oacc[mt][nt], ph[mt], vh[nt]);
                mma16816(oacc[mt][nt], pl[mt], vh[nt]);
                mma16816(oacc[mt][nt], ph[mt], vl[nt]);
            }
    }
    __syncthreads();   // P/V buffers free; reuse R for partials

    // ---- 8-way reduction: partials [w][32][64] fp32 in smem ----
    float* Pt = (float*)(sm + ATT_R_OFF);
#pragma unroll
    for (int mt = 0; mt < 2; mt++)
#pragma unroll
        for (int nt = 0; nt < 8; nt++) {
            int r0 = mt * 16 + er;
            int c0 = nt * 8 + ec;
            *(float2*)&Pt[wid * 2048 + r0 * 64 + c0] =
                make_float2(oacc[mt][nt][0], oacc[mt][nt][1]);
            *(float2*)&Pt[wid * 2048 + (r0 + 8) * 64 + c0] =
                make_float2(oacc[mt][nt][2], oacc[mt][nt][3]);
        }
    __syncthreads();

    {
        int r = tid >> 3;             // 0..31
        int c0 = (tid & 7) * 8;       // 0..56
        float s[8];
#pragma unroll
        for (int j = 0; j < 8; j += 4) {
            float4 v = *(const float4*)&Pt[r * 64 + c0 + j];
            s[j] = v.x; s[j + 1] = v.y; s[j + 2] = v.z; s[j + 3] = v.w;
        }
#pragma unroll
        for (int w = 1; w < 8; w++) {
#pragma unroll
            for (int j = 0; j < 8; j += 4) {
                float4 v = *(const float4*)&Pt[w * 2048 + r * 64 + c0 + j];
                s[j] += v.x; s[j + 1] += v.y; s[j + 2] += v.z; s[j + 3] += v.w;
            }
        }
        int t1 = qt * 32 + r;
        int p = t1 >> 4, qq = t1 & 15;
        int off = (b * 1024 + h * 64 + p) * 1024 + qq * 64 + c0;
        __nv_bfloat162 hp[4], lp[4];
#pragma unroll
        for (int j = 0; j < 4; j++) {
            __nv_bfloat16 h0 = __float2bfloat16(s[2 * j]);
            __nv_bfloat16 h1 = __float2bfloat16(s[2 * j + 1]);
            hp[j].x = h0; hp[j].y = h1;
            lp[j].x = __float2bfloat16(s[2 * j] - __bfloat162float(h0));
            lp[j].y = __float2bfloat16(s[2 * j + 1] - __bfloat162float(h1));
        }
        *(uint4*)(g_Ahi + off) = *(uint4*)hp;
        *(uint4*)(g_Alo + off) = *(uint4*)lp;
    }
}

// ===========================================================================
extern "C" void kernel_launch(void* const* d_in, const int* in_sizes, int n_in,
                              void* d_out, int out_size) {
    const float* x  = (const float*)d_in[0];
    const float* Wq = (const float*)d_in[1];
    const float* bq = (const float*)d_in[2];
    const float* Wk = (const float*)d_in[3];
    const float* bk = (const float*)d_in[4];
    const float* Wv = (const float*)d_in[5];
    const float* bv = (const float*)d_in[6];
    const float* Wo = (const float*)d_in[7];
    const float* bo = (const float*)d_in[8];
    float* out = (float*)d_out;

    __nv_bfloat16 *xhi, *xlo, *whi, *wlo;
    __nv_bfloat16 *qthi, *kthi, *vhi, *vlo, *ahi, *alo;
    cudaGetSymbolAddress((void**)&xhi, g_xhi);
    cudaGetSymbolAddress((void**)&xlo, g_xlo);
    cudaGetSymbolAddress((void**)&whi, g_wt_hi);
    cudaGetSymbolAddress((void**)&wlo, g_wt_lo);
    cudaGetSymbolAddress((void**)&qthi, g_QThi);
    cudaGetSymbolAddress((void**)&kthi, g_KThi);
    cudaGetSymbolAddress((void**)&vhi, g_Vhi);
    cudaGetSymbolAddress((void**)&vlo, g_Vlo);
    cudaGetSymbolAddress((void**)&ahi, g_Ahi);
    cudaGetSymbolAddress((void**)&alo, g_Alo);

    cudaFuncSetAttribute(gemm_mma_kernel<1>, cudaFuncAttributeMaxDynamicSharedMemorySize,
                         GSMEM_BYTES);
    cudaFuncSetAttribute(gemm_mma_kernel<3>, cudaFuncAttributeMaxDynamicSharedMemorySize,
                         GSMEM_BYTES);
    cudaFuncSetAttribute(attn_mma_kernel, cudaFuncAttributeMaxDynamicSharedMemorySize,
                         ATT_SMEM);

    // 1) split x
    split_f32_kernel<<<2048, 256>>>(x, xhi, xlo, BLN * DIM / 4);

    // 2) transpose+split weights (W^T [n][k])
    dim3 tgrid(32, 32), tblk(32, 8);
    transpose_split_kernel<<<tgrid, tblk>>>(Wq, whi + 0 * DIM * DIM, wlo + 0 * DIM * DIM);
    transpose_split_kernel<<<tgrid, tblk>>>(Wk, whi + 1 * DIM * DIM, wlo + 1 * DIM * DIM);
    transpose_split_kernel<<<tgrid, tblk>>>(Wv, whi + 2 * DIM * DIM, wlo + 2 * DIM * DIM);
    transpose_split_kernel<<<tgrid, tblk>>>(Wo, whi + 3 * DIM * DIM, wlo + 3 * DIM * DIM);

    // 3) projections: Q,K 1-term transposed-hi; V 3-term natural split
    dim3 ggrid(8, 64);
    gemm_mma_kernel<1><<<ggrid, 256, GSMEM_BYTES>>>(xhi, xlo, whi + 0 * DIM * DIM,
                                                    wlo + 0 * DIM * DIM, bq,
                                                    nullptr, qthi, nullptr, QKSCALE, 2);
    gemm_mma_kernel<1><<<ggrid, 256, GSMEM_BYTES>>>(xhi, xlo, whi + 1 * DIM * DIM,
                                                    wlo + 1 * DIM * DIM, bk,
                                                    nullptr, kthi, nullptr, QKSCALE, 2);
    gemm_mma_kernel<3><<<ggrid, 256, GSMEM_BYTES>>>(xhi, xlo, whi + 2 * DIM * DIM,
                                                    wlo + 2 * DIM * DIM, bv,
                                                    nullptr, vhi, vlo, 1.0f, 1);

    // 4) attention
    attn_mma_kernel<<<dim3(32, 128), 256, ATT_SMEM>>>();

    // 5) output projection (3-term, fp32 out)
    gemm_mma_kernel<3><<<ggrid, 256, GSMEM_BYTES>>>(ahi, alo, whi + 3 * DIM * DIM,
                                                    wlo + 3 * DIM * DIM, bo,
                                                    out, nullptr, nullptr, 1.0f, 0);
}

// round 8
// speedup vs baseline: 3.9986x; 1.5583x over previous
#include <cuda_runtime.h>
#include <cuda_bf16.h>
#include <cstdint>

// ===========================================================================
// Problem constants
// ===========================================================================
#define BLN 8192          // B*L
#define DIM 1024          // D
#define QKSCALE 0.03125f  // 1/sqrt(1024)

// ===========================================================================
// Device scratch (allocation-free rule: device globals)
// ===========================================================================
__device__ __nv_bfloat16 g_xhi[BLN * DIM];
__device__ __nv_bfloat16 g_xlo[BLN * DIM];
__device__ __nv_bfloat16 g_wt_hi[4][DIM * DIM];   // W^T [n][k] hi
__device__ __nv_bfloat16 g_wt_lo[4][DIM * DIM];   // W^T [n][k] lo
// Batch-transposed Q,K (hi only — 1-term path): [b][ch=t][l]
__device__ __nv_bfloat16 g_QThi[BLN * DIM];
__device__ __nv_bfloat16 g_KThi[BLN * DIM];
// Natural split V and attention output A: [row=(b,l)][ch]
__device__ __nv_bfloat16 g_Vhi[BLN * DIM];
__device__ __nv_bfloat16 g_Vlo[BLN * DIM];
__device__ __nv_bfloat16 g_Ahi[BLN * DIM];
__device__ __nv_bfloat16 g_Alo[BLN * DIM];

// ===========================================================================
// PTX helpers (sm_80-era: target is plain sm_100, tcgen05 unavailable)
// ===========================================================================
__device__ __forceinline__ uint32_t smem_u32(const void* p) {
    uint32_t a;
    asm("{ .reg .u64 t; cvta.to.shared.u64 t, %1; cvt.u32.u64 %0, t; }" : "=r"(a) : "l"(p));
    return a;
}
#define CP_ASYNC16(saddr, gptr) \
    asm volatile("cp.async.cg.shared.global [%0], [%1], 16;" :: "r"(saddr), "l"(gptr))
#define CP_COMMIT() asm volatile("cp.async.commit_group;" ::: "memory")
#define CP_WAIT(n)  asm volatile("cp.async.wait_group %0;" :: "n"(n) : "memory")

__device__ __forceinline__ void ldmx4(uint32_t& r0, uint32_t& r1, uint32_t& r2, uint32_t& r3,
                                      uint32_t addr) {
    asm volatile("ldmatrix.sync.aligned.m8n8.x4.shared.b16 {%0,%1,%2,%3}, [%4];"
                 : "=r"(r0), "=r"(r1), "=r"(r2), "=r"(r3) : "r"(addr));
}
__device__ __forceinline__ void ldmx2(uint32_t& r0, uint32_t& r1, uint32_t addr) {
    asm volatile("ldmatrix.sync.aligned.m8n8.x2.shared.b16 {%0,%1}, [%2];"
                 : "=r"(r0), "=r"(r1) : "r"(addr));
}
__device__ __forceinline__ void mma16816(float* c, const uint32_t* a, const uint32_t* b) {
    asm volatile(
        "mma.sync.aligned.m16n8k16.row.col.f32.bf16.bf16.f32 "
        "{%0,%1,%2,%3}, {%4,%5,%6,%7}, {%8,%9}, {%0,%1,%2,%3};"
        : "+f"(c[0]), "+f"(c[1]), "+f"(c[2]), "+f"(c[3])
        : "r"(a[0]), "r"(a[1]), "r"(a[2]), "r"(a[3]), "r"(b[0]), "r"(b[1]));
}
__device__ __forceinline__ void pack_split(float v0, float v1, uint32_t& hi, uint32_t& lo) {
    __nv_bfloat16 h0 = __float2bfloat16(v0);
    __nv_bfloat16 h1 = __float2bfloat16(v1);
    __nv_bfloat162 hp; hp.x = h0; hp.y = h1;
    hi = *(uint32_t*)&hp;
    __nv_bfloat162 lp;
    lp.x = __float2bfloat16(v0 - __bfloat162float(h0));
    lp.y = __float2bfloat16(v1 - __bfloat162float(h1));
    lo = *(uint32_t*)&lp;
}

// ===========================================================================
// Split f32 -> (bf16 hi, bf16 lo)
// ===========================================================================
struct alignas(8) bf4 { __nv_bfloat16 a, b, c, d; };

__global__ void split_f32_kernel(const float* __restrict__ in,
                                 __nv_bfloat16* __restrict__ hi,
                                 __nv_bfloat16* __restrict__ lo, int n4) {
    int i = blockIdx.x * blockDim.x + threadIdx.x;
    int stride = gridDim.x * blockDim.x;
    for (; i < n4; i += stride) {
        float4 v = ((const float4*)in)[i];
        __nv_bfloat16 h0 = __float2bfloat16(v.x);
        __nv_bfloat16 h1 = __float2bfloat16(v.y);
        __nv_bfloat16 h2 = __float2bfloat16(v.z);
        __nv_bfloat16 h3 = __float2bfloat16(v.w);
        bf4 H = {h0, h1, h2, h3};
        bf4 L = {__float2bfloat16(v.x - __bfloat162float(h0)),
                 __float2bfloat16(v.y - __bfloat162float(h1)),
                 __float2bfloat16(v.z - __bfloat162float(h2)),
                 __float2bfloat16(v.w - __bfloat162float(h3))};
        ((bf4*)hi)[i] = H;
        ((bf4*)lo)[i] = L;
    }
}

// ===========================================================================
// Transpose + split: W [K][N] f32 -> W^T [N][K] bf16 hi/lo
// ===========================================================================
__global__ void transpose_split_kernel(const float* __restrict__ W,
                                       __nv_bfloat16* __restrict__ Thi,
                                       __nv_bfloat16* __restrict__ Tlo) {
    __shared__ float t[32][33];
    const int n0 = blockIdx.x << 5;
    const int k0 = blockIdx.y << 5;
    const int tx = threadIdx.x, ty = threadIdx.y;
#pragma unroll
    for (int j = 0; j < 4; j++)
        t[ty + (j << 3)][tx] = W[(k0 + ty + (j << 3)) * DIM + n0 + tx];
    __syncthreads();
#pragma unroll
    for (int j = 0; j < 4; j++) {
        float v = t[tx][ty + (j << 3)];
        __nv_bfloat16 h = __float2bfloat16(v);
        int o = (n0 + ty + (j << 3)) * DIM + k0 + tx;
        Thi[o] = h;
        Tlo[o] = __float2bfloat16(v - __bfloat162float(h));
    }
}

// ===========================================================================
// Tensor-core GEMM via mma.sync, TERMS split terms, 3-stage cp.async pipeline.
// modes: 0 = fp32 natural; 1 = split-bf16 natural; 2 = bf16 transposed [b][ch][l]
// (unchanged from round 7)
// ===========================================================================
#define GSTRIDE 40
#define GTILE_BYTES (128 * GSTRIDE * 2)
#define GSTAGE_BYTES (4 * GTILE_BYTES)
#define GSMEM_BYTES (3 * GSTAGE_BYTES)   // 122880 B (3 stages)

template <int TERMS>
__global__ __launch_bounds__(256, 1)
void gemm_mma_kernel(const __nv_bfloat16* __restrict__ Ahi,
                     const __nv_bfloat16* __restrict__ Alo,
                     const __nv_bfloat16* __restrict__ Bhi,
                     const __nv_bfloat16* __restrict__ Blo,
                     const float* __restrict__ bias,
                     float* __restrict__ Cf,
                     __nv_bfloat16* __restrict__ Chi,
                     __nv_bfloat16* __restrict__ Clo,
                     float scale, int mode) {
    extern __shared__ __align__(16) char smem[];
    const uint32_t sbase = smem_u32(smem);

    const int tid = threadIdx.x;
    const int wid = tid >> 5;
    const int lane = tid & 31;
    const int m0 = blockIdx.y << 7;
    const int n0 = blockIdx.x << 7;
    const int wm = (wid & 1) << 6;
    const int wn = (wid >> 1) << 5;

    const __nv_bfloat16* srcs[4] = {Ahi + m0 * 1024, Alo + m0 * 1024,
                                    Bhi + n0 * 1024, Blo + n0 * 1024};

    float acc[4][4][4];
#pragma unroll
    for (int a = 0; a < 4; a++)
#pragma unroll
        for (int b = 0; b < 4; b++)
#pragma unroll
            for (int c = 0; c < 4; c++) acc[a][b][c] = 0.f;

    const int a_r = lane & 15, a_k = lane >> 4;
    const int b_r = lane & 7, b_k = (lane >> 3) & 1;

    auto load_stage = [&](int kt, int buf) {
        const int kb = kt << 5;
        uint32_t sb = sbase + buf * GSTAGE_BYTES;
        constexpr int NLD = (TERMS == 3) ? 8 : 4;
#pragma unroll
        for (int i = 0; i < NLD; i++) {
            int tile, idx;
            if (TERMS == 3) {
                tile = i >> 1;
                idx = ((i & 1) << 8) + tid;
            } else {
                tile = (i >> 1) << 1;       // 0 (Ahi) or 2 (Bhi)
                idx = ((i & 1) << 8) + tid;
            }
            int row = idx >> 2;
            int ch = idx & 3;
            const __nv_bfloat16* g = srcs[tile] + row * 1024 + kb + (ch << 3);
            uint32_t s = sb + tile * GTILE_BYTES + (row * GSTRIDE + (ch << 3)) * 2;
            CP_ASYNC16(s, g);
        }
    };

    load_stage(0, 0); CP_COMMIT();
    load_stage(1, 1); CP_COMMIT();

    for (int kt = 0; kt < 32; kt++) {
        if (kt == 31) { CP_WAIT(0); } else { CP_WAIT(1); }
        __syncthreads();
        if (kt + 2 < 32) { load_stage(kt + 2, (kt + 2) % 3); CP_COMMIT(); }

        const uint32_t sb = sbase + (kt % 3) * GSTAGE_BYTES;
        const uint32_t sAhi = sb;
        const uint32_t sAlo = sb + GTILE_BYTES;
        const uint32_t sBhi = sb + 2 * GTILE_BYTES;
        const uint32_t sBlo = sb + 3 * GTILE_BYTES;

#pragma unroll
        for (int ks = 0; ks < 2; ks++) {
            uint32_t ah[4][4], al[4][4], bh[4][2], bl[4][2];
#pragma unroll
            for (int mt = 0; mt < 4; mt++) {
                uint32_t off = ((wm + (mt << 4) + a_r) * GSTRIDE + (ks << 4) + (a_k << 3)) * 2;
                ldmx4(ah[mt][0], ah[mt][1], ah[mt][2], ah[mt][3], sAhi + off);
                if (TERMS == 3)
                    ldmx4(al[mt][0], al[mt][1], al[mt][2], al[mt][3], sAlo + off);
            }
#pragma unroll
            for (int nt = 0; nt < 4; nt++) {
                uint32_t off = ((wn + (nt << 3) + b_r) * GSTRIDE + (ks << 4) + (b_k << 3)) * 2;
                ldmx2(bh[nt][0], bh[nt][1], sBhi + off);
                if (TERMS == 3)
                    ldmx2(bl[nt][0], bl[nt][1], sBlo + off);
            }
#pragma unroll
            for (int mt = 0; mt < 4; mt++)
#pragma unroll
                for (int nt = 0; nt < 4; nt++) {
                    mma16816(acc[mt][nt], ah[mt], bh[nt]);
                    if (TERMS == 3) {
                        mma16816(acc[mt][nt], al[mt], bh[nt]);
                        mma16816(acc[mt][nt], ah[mt], bl[nt]);
                    }
                }
        }
    }
    __syncthreads();

    const int er = lane >> 2;
    const int ec = (lane & 3) << 1;

    if (mode == 0) {
#pragma unroll
        for (int mt = 0; mt < 4; mt++) {
#pragma unroll
            for (int nt = 0; nt < 4; nt++) {
                int row = m0 + wm + (mt << 4) + er;
                int col = n0 + wn + (nt << 3) + ec;
                float2 b2 = *(const float2*)(bias + col);
                float2 o0, o1;
                o0.x = (acc[mt][nt][0] + b2.x) * scale;
                o0.y = (acc[mt][nt][1] + b2.y) * scale;
                o1.x = (acc[mt][nt][2] + b2.x) * scale;
                o1.y = (acc[mt][nt][3] + b2.y) * scale;
                *(float2*)(Cf + row * 1024 + col) = o0;
                *(float2*)(Cf + (row + 8) * 1024 + col) = o1;
            }
        }
    } else if (mode == 1) {
#pragma unroll
        for (int mt = 0; mt < 4; mt++) {
#pragma unroll
            for (int nt = 0; nt < 4; nt++) {
                int row = m0 + wm + (mt << 4) + er;
                int col = n0 + wn + (nt << 3) + ec;
                float2 b2 = *(const float2*)(bias + col);
#pragma unroll
                for (int half = 0; half < 2; half++) {
                    int r = row + half * 8;
                    float v0 = (acc[mt][nt][half * 2 + 0] + b2.x) * scale;
                    float v1 = (acc[mt][nt][half * 2 + 1] + b2.y) * scale;
                    uint32_t hp, lp;
                    pack_split(v0, v1, hp, lp);
                    *(uint32_t*)(Chi + r * 1024 + col) = hp;
                    *(uint32_t*)(Clo + r * 1024 + col) = lp;
                }
            }
        }
    } else {
        __nv_bfloat16* sthi = (__nv_bfloat16*)smem;
        __nv_bfloat16* stlo = (__nv_bfloat16*)(smem + 34816);
#pragma unroll
        for (int mt = 0; mt < 4; mt++) {
#pragma unroll
            for (int nt = 0; nt < 4; nt++) {
                int mrow = wm + (mt << 4) + er;
                int ncol = wn + (nt << 3) + ec;
                float2 b2 = *(const float2*)(bias + n0 + ncol);
#pragma unroll
                for (int half = 0; half < 2; half++) {
                    int r = mrow + half * 8;
                    float v0 = (acc[mt][nt][half * 2 + 0] + b2.x) * scale;
                    float v1 = (acc[mt][nt][half * 2 + 1] + b2.y) * scale;
                    __nv_bfloat16 h0 = __float2bfloat16(v0);
                    __nv_bfloat16 h1 = __float2bfloat16(v1);
                    sthi[ncol * 136 + r] = h0;
                    sthi[(ncol + 1) * 136 + r] = h1;
                    if (TERMS == 3) {
                        stlo[ncol * 136 + r] = __float2bfloat16(v0 - __bfloat162float(h0));
                        stlo[(ncol + 1) * 136 + r] = __float2bfloat16(v1 - __bfloat162float(h1));
                    }
                }
            }
        }
        __syncthreads();
        const int bidx = m0 >> 10;
        const int l0 = m0 & 1023;
        constexpr int NCP = (TERMS == 3) ? 16 : 8;
#pragma unroll
        for (int i = 0; i < NCP; i++) {
            int q = tid + (i << 8);
            int t = q >> 11;
            int idx = q & 2047;
            int nrow = idx >> 4;
            int ch = idx & 15;
            uint4 v = *(const uint4*)(smem + t * 34816 + (nrow * 136 + ch * 8) * 2);
            __nv_bfloat16* dst = (t ? Clo : Chi) +
                bidx * 1048576 + (n0 + nrow) * 1024 + l0 + ch * 8;
            *(uint4*)dst = v;
        }
    }
}

// ===========================================================================
// FlashAttention-2-style attention, register-resident, online softmax.
// CTA = (group g=(b,h), 128 t1-rows). Warp w owns rows w*16..w*16+15 over the
// FULL t2 range — no cross-warp reduction, no S smem.
// Phase QK: 1-term bf16 (S absolute-error regime). Phase PV: 3-term split,
// P packed hi/lo in registers from the S accumulator (C-frag == A-frag trick).
// ===========================================================================
#define ATT_Q_OFF 0                 // Q hi [128][72]            18432 B
#define ATT_K_OFF 18432             // K hi [128][72] x2 bufs    36864 B
#define ATT_V_OFF 55296             // V hi+lo [64][136] x2 bufs 69632 B
#define ATT_SMEM  124928

__global__ __launch_bounds__(256, 1)
void attn_fa2_kernel() {
    extern __shared__ __align__(16) char sm[];
    const uint32_t R = smem_u32(sm);

    const int g = blockIdx.y, qt = blockIdx.x;   // qt: 0..7 (128 rows each)
    const int b = g >> 4, h = g & 15;
    const int tid = threadIdx.x, wid = tid >> 5, lane = tid & 31;

    const int a_r = lane & 15, a_k = lane >> 4;
    const int b_r = lane & 7, b_k = (lane >> 3) & 1;
    const int ec = (lane & 3) << 1;
    const int er = lane >> 2;

    const int qkrow = b * 1048576 + h * 64;   // + t*1024 gives QT/KT row t, d-cols at l=h*64

    // ---- prologue loads: Q tile + K0 + V0 ----
#pragma unroll
    for (int i = 0; i < 4; i++) {
        int q = tid + (i << 8);           // 0..1023
        int r = q >> 3, ch = q & 7;
        const __nv_bfloat16* src = g_QThi + qkrow + (qt * 128 + r) * 1024 + ch * 8;
        CP_ASYNC16(R + ATT_Q_OFF + (r * 72 + ch * 8) * 2, src);
    }
    auto load_K = [&](int c, int buf) {
#pragma unroll
        for (int i = 0; i < 4; i++) {
            int q = tid + (i << 8);
            int r = q >> 3, ch = q & 7;
            const __nv_bfloat16* src = g_KThi + qkrow + (c * 128 + r) * 1024 + ch * 8;
            CP_ASYNC16(R + ATT_K_OFF + buf * 18432 + (r * 72 + ch * 8) * 2, src);
        }
    };
    auto load_V = [&](int c, int buf) {
#pragma unroll
        for (int i = 0; i < 8; i++) {
            int q = tid + (i << 8);
            int t = q >> 10, idx = q & 1023;
            int r = idx >> 4, ch = idx & 15;   // r = d (0..63), ch*8 = t2 within chunk
            const __nv_bfloat16* src =
                (t ? g_Vlo : g_Vhi) + (b * 1024 + h * 64 + r) * 1024 + c * 128 + ch * 8;
            CP_ASYNC16(R + ATT_V_OFF + buf * 34816 + t * 17408 + (r * 136 + ch * 8) * 2, src);
        }
    };
    load_K(0, 0);
    load_V(0, 0);
    CP_COMMIT();
    CP_WAIT(0);
    __syncthreads();

    // hoist Q fragments (rows wid*16..+15, k = d 0..63)
    uint32_t qh[4][4];
#pragma unroll
    for (int ks = 0; ks < 4; ks++) {
        uint32_t off = R + ATT_Q_OFF + ((wid * 16 + a_r) * 72 + ks * 16 + a_k * 8) * 2;
        ldmx4(qh[ks][0], qh[ks][1], qh[ks][2], qh[ks][3], off);
    }

    float oacc[8][4];
#pragma unroll
    for (int i = 0; i < 8; i++)
#pragma unroll
        for (int j = 0; j < 4; j++) oacc[i][j] = 0.f;
    float mrow[2] = {-1e30f, -1e30f};   // running max, rows er / er+8
    float lrow[2] = {0.f, 0.f};         // running sum

    for (int c = 0; c < 8; c++) {
        const int buf = c & 1;
        if (c + 1 < 8) {
            load_K(c + 1, buf ^ 1);
            load_V(c + 1, buf ^ 1);
            CP_COMMIT();
        }

        // ---- QK: S[16][128] in registers (1-term) ----
        float sacc[16][4];
#pragma unroll
        for (int i = 0; i < 16; i++)
#pragma unroll
            for (int j = 0; j < 4; j++) sacc[i][j] = 0.f;

        const uint32_t kb = R + ATT_K_OFF + buf * 18432;
#pragma unroll
        for (int ks = 0; ks < 4; ks++) {
#pragma unroll
            for (int nt = 0; nt < 16; nt++) {
                uint32_t bb[2];
                ldmx2(bb[0], bb[1], kb + ((nt * 8 + b_r) * 72 + ks * 16 + b_k * 8) * 2);
                mma16816(sacc[nt], qh[ks], bb);
            }
        }

        // ---- online softmax update ----
        float cm[2];
#pragma unroll
        for (int rr = 0; rr < 2; rr++) {
            float mx = -1e30f;
#pragma unroll
            for (int nt = 0; nt < 16; nt++)
                mx = fmaxf(mx, fmaxf(sacc[nt][rr * 2], sacc[nt][rr * 2 + 1]));
            mx = fmaxf(mx, __shfl_xor_sync(0xffffffffu, mx, 1));
            mx = fmaxf(mx, __shfl_xor_sync(0xffffffffu, mx, 2));
            float mnew = fmaxf(mrow[rr], mx);
            cm[rr] = __expf(mrow[rr] - mnew);
            mrow[rr] = mnew;
        }
        float rs0 = 0.f, rs1 = 0.f;
#pragma unroll
        for (int nt = 0; nt < 16; nt++) {
            sacc[nt][0] = __expf(sacc[nt][0] - mrow[0]);
            sacc[nt][1] = __expf(sacc[nt][1] - mrow[0]);
            sacc[nt][2] = __expf(sacc[nt][2] - mrow[1]);
            sacc[nt][3] = __expf(sacc[nt][3] - mrow[1]);
            rs0 += sacc[nt][0] + sacc[nt][1];
            rs1 += sacc[nt][2] + sacc[nt][3];
        }
        rs0 += __shfl_xor_sync(0xffffffffu, rs0, 1);
        rs0 += __shfl_xor_sync(0xffffffffu, rs0, 2);
        rs1 += __shfl_xor_sync(0xffffffffu, rs1, 1);
        rs1 += __shfl_xor_sync(0xffffffffu, rs1, 2);
        lrow[0] = lrow[0] * cm[0] + rs0;
        lrow[1] = lrow[1] * cm[1] + rs1;

        // rescale O accumulators
#pragma unroll
        for (int nt = 0; nt < 8; nt++) {
            oacc[nt][0] *= cm[0]; oacc[nt][1] *= cm[0];
            oacc[nt][2] *= cm[1]; oacc[nt][3] *= cm[1];
        }

        // ---- pack P̃ into A fragments (C-frag == A-frag layout), hi + lo ----
        uint32_t ph[8][4], pl[8][4];
#pragma unroll
        for (int j = 0; j < 8; j++) {
            pack_split(sacc[2 * j][0],     sacc[2 * j][1],     ph[j][0], pl[j][0]);
            pack_split(sacc[2 * j][2],     sacc[2 * j][3],     ph[j][1], pl[j][1]);
            pack_split(sacc[2 * j + 1][0], sacc[2 * j + 1][1], ph[j][2], pl[j][2]);
            pack_split(sacc[2 * j + 1][2], sacc[2 * j + 1][3], ph[j][3], pl[j][3]);
        }

        // ---- PV: O += P̃ V (3-term split) ----
        const uint32_t vb = R + ATT_V_OFF + buf * 34816;
#pragma unroll
        for (int ks = 0; ks < 8; ks++) {
#pragma unroll
            for (int nt = 0; nt < 8; nt++) {
                uint32_t vh[2], vl[2];
                uint32_t voff = vb + ((nt * 8 + b_r) * 136 + ks * 16 + b_k * 8) * 2;
                ldmx2(vh[0], vh[1], voff);
                ldmx2(vl[0], vl[1], voff + 17408);
                mma16816(oacc[nt], ph[ks], vh);
                mma16816(oacc[nt], pl[ks], vh);
                mma16816(oacc[nt], ph[ks], vl);
            }
        }

        if (c + 1 < 8) { CP_WAIT(0); __syncthreads(); }
    }

    // ---- epilogue: normalize by l, write split bf16 with reference scatter ----
    float inv[2] = {1.f / lrow[0], 1.f / lrow[1]};
#pragma unroll
    for (int nt = 0; nt < 8; nt++) {
#pragma unroll
        for (int half = 0; half < 2; half++) {
            int t1 = qt * 128 + wid * 16 + er + half * 8;
            int p = t1 >> 4, qq = t1 & 15;
            int col = nt * 8 + ec;
            float v0 = oacc[nt][half * 2 + 0] * inv[half];
            float v1 = oacc[nt][half * 2 + 1] * inv[half];
            uint32_t hp, lp;
            pack_split(v0, v1, hp, lp);
            int off = (b * 1024 + h * 64 + p) * 1024 + qq * 64 + col;
            *(uint32_t*)(g_Ahi + off) = hp;
            *(uint32_t*)(g_Alo + off) = lp;
        }
    }
}

// ===========================================================================
extern "C" void kernel_launch(void* const* d_in, const int* in_sizes, int n_in,
                              void* d_out, int out_size) {
    const float* x  = (const float*)d_in[0];
    const float* Wq = (const float*)d_in[1];
    const float* bq = (const float*)d_in[2];
    const float* Wk = (const float*)d_in[3];
    const float* bk = (const float*)d_in[4];
    const float* Wv = (const float*)d_in[5];
    const float* bv = (const float*)d_in[6];
    const float* Wo = (const float*)d_in[7];
    const float* bo = (const float*)d_in[8];
    float* out = (float*)d_out;

    __nv_bfloat16 *xhi, *xlo, *whi, *wlo;
    __nv_bfloat16 *qthi, *kthi, *vhi, *vlo, *ahi, *alo;
    cudaGetSymbolAddress((void**)&xhi, g_xhi);
    cudaGetSymbolAddress((void**)&xlo, g_xlo);
    cudaGetSymbolAddress((void**)&whi, g_wt_hi);
    cudaGetSymbolAddress((void**)&wlo, g_wt_lo);
    cudaGetSymbolAddress((void**)&qthi, g_QThi);
    cudaGetSymbolAddress((void**)&kthi, g_KThi);
    cudaGetSymbolAddress((void**)&vhi, g_Vhi);
    cudaGetSymbolAddress((void**)&vlo, g_Vlo);
    cudaGetSymbolAddress((void**)&ahi, g_Ahi);
    cudaGetSymbolAddress((void**)&alo, g_Alo);

    cudaFuncSetAttribute(gemm_mma_kernel<1>, cudaFuncAttributeMaxDynamicSharedMemorySize,
                         GSMEM_BYTES);
    cudaFuncSetAttribute(gemm_mma_kernel<3>, cudaFuncAttributeMaxDynamicSharedMemorySize,
                         GSMEM_BYTES);
    cudaFuncSetAttribute(attn_fa2_kernel, cudaFuncAttributeMaxDynamicSharedMemorySize,
                         ATT_SMEM);

    // 1) split x
    split_f32_kernel<<<2048, 256>>>(x, xhi, xlo, BLN * DIM / 4);

    // 2) transpose+split weights (W^T [n][k])
    dim3 tgrid(32, 32), tblk(32, 8);
    transpose_split_kernel<<<tgrid, tblk>>>(Wq, whi + 0 * DIM * DIM, wlo + 0 * DIM * DIM);
    transpose_split_kernel<<<tgrid, tblk>>>(Wk, whi + 1 * DIM * DIM, wlo + 1 * DIM * DIM);
    transpose_split_kernel<<<tgrid, tblk>>>(Wv, whi + 2 * DIM * DIM, wlo + 2 * DIM * DIM);
    transpose_split_kernel<<<tgrid, tblk>>>(Wo, whi + 3 * DIM * DIM, wlo + 3 * DIM * DIM);

    // 3) projections: Q,K 1-term transposed-hi; V 3-term natural split
    dim3 ggrid(8, 64);
    gemm_mma_kernel<1><<<ggrid, 256, GSMEM_BYTES>>>(xhi, xlo, whi + 0 * DIM * DIM,
                                                    wlo + 0 * DIM * DIM, bq,
                                                    nullptr, qthi, nullptr, QKSCALE, 2);
    gemm_mma_kernel<1><<<ggrid, 256, GSMEM_BYTES>>>(xhi, xlo, whi + 1 * DIM * DIM,
                                                    wlo + 1 * DIM * DIM, bk,
                                                    nullptr, kthi, nullptr, QKSCALE, 2);
    gemm_mma_kernel<3><<<ggrid, 256, GSMEM_BYTES>>>(xhi, xlo, whi + 2 * DIM * DIM,
                                                    wlo + 2 * DIM * DIM, bv,
                                                    nullptr, vhi, vlo, 1.0f, 1);

    // 4) attention (FA2-style, t1=128 per CTA)
    attn_fa2_kernel<<<dim3(8, 128), 256, ATT_SMEM>>>();

    // 5) output projection (3-term, fp32 out)
    gemm_mma_kernel<3><<<ggrid, 256, GSMEM_BYTES>>>(ahi, alo, whi + 3 * DIM * DIM,
                                                    wlo + 3 * DIM * DIM, bo,
                                                    out, nullptr, nullptr, 1.0f, 0);
}